// round 1
// baseline (speedup 1.0000x reference)
#include <cuda_runtime.h>
#include <math.h>

#define NN    100000
#define DEG   16
#define FDIM  16
#define PDIM  3
#define HDIM  64
#define RREG  8
#define DIN1  19

// -------- scratch (no allocations allowed; static device globals) --------
__device__ float g_A[NN * HDIM];      // per-node "center" term
__device__ float g_B[NN * HDIM];      // per-node "neighbor" term
__device__ float g_h[NN * HDIM];      // conv1 output
__device__ float g_qsum[RREG * HDIM]; // region feature sums
__device__ int   g_qcnt[RREG];        // region counts

// ---------------------------------------------------------------------
__global__ void init_kernel() {
    int t = threadIdx.x;
    if (t < RREG * HDIM) g_qsum[t] = 0.f;
    if (t < RREG)        g_qcnt[t] = 0;
}

__global__ void count_kernel(const int* __restrict__ labels) {
    __shared__ int hist[RREG];
    if (threadIdx.x < RREG) hist[threadIdx.x] = 0;
    __syncthreads();
    int stride = gridDim.x * blockDim.x;
    for (int i = blockIdx.x * blockDim.x + threadIdx.x; i < NN; i += stride)
        atomicAdd(&hist[labels[i]], 1);
    __syncthreads();
    if (threadIdx.x < RREG) atomicAdd(&g_qcnt[threadIdx.x], hist[threadIdx.x]);
}

// conv1 node transform: f = [x, pos] (19 dims)
// A[i] = f_i @ (W1a - W1b) + b1 ;  B[i] = f_i @ W1b
__global__ void node1_kernel(const float* __restrict__ x, const float* __restrict__ pos,
                             const float* __restrict__ W1, const float* __restrict__ b1) {
    __shared__ float sW[2 * DIN1 * HDIM];
    for (int j = threadIdx.x; j < DIN1 * HDIM; j += blockDim.x) {
        float wb = W1[j + DIN1 * HDIM];
        sW[j] = W1[j] - wb;            // diff part
        sW[j + DIN1 * HDIM] = wb;      // neighbor part
    }
    __syncthreads();
    int stride = gridDim.x * blockDim.x;
    for (int idx = blockIdx.x * blockDim.x + threadIdx.x; idx < NN * HDIM; idx += stride) {
        int i = idx >> 6;
        int c = idx & 63;
        float a = 0.f, b = 0.f;
#pragma unroll
        for (int k = 0; k < DIN1; k++) {
            float f = (k < FDIM) ? __ldg(x + i * FDIM + k)
                                 : __ldg(pos + i * PDIM + (k - FDIM));
            a = fmaf(f, sW[k * HDIM + c], a);
            b = fmaf(f, sW[(k + DIN1) * HDIM + c], b);
        }
        g_A[idx] = a + __ldg(b1 + c);
        g_B[idx] = b;
    }
}

// conv2 node transform: input = g_h (64 dims)
__global__ void node2_kernel(const float* __restrict__ W1, const float* __restrict__ b1) {
    __shared__ float sW[2 * HDIM * HDIM];
    for (int j = threadIdx.x; j < HDIM * HDIM; j += blockDim.x) {
        float wb = W1[j + HDIM * HDIM];
        sW[j] = W1[j] - wb;
        sW[j + HDIM * HDIM] = wb;
    }
    __syncthreads();
    int stride = gridDim.x * blockDim.x;
    for (int idx = blockIdx.x * blockDim.x + threadIdx.x; idx < NN * HDIM; idx += stride) {
        int i = idx >> 6;
        int c = idx & 63;
        float a = 0.f, b = 0.f;
#pragma unroll
        for (int k = 0; k < HDIM; k++) {
            float f = __ldg(g_h + i * HDIM + k);   // uniform per warp -> broadcast
            a = fmaf(f, sW[k * HDIM + c], a);
            b = fmaf(f, sW[(k + HDIM) * HDIM + c], b);
        }
        g_A[idx] = a + __ldg(b1 + c);
        g_B[idx] = b;
    }
}

// Edge kernel: warp per node, lane owns output cols (lane, lane+32).
// out[i][c] = relu( max_e( relu(A[i]+B[src_e]) @ W2 )[c] + b2[c] )
// REGION=false: store to g_h.  REGION=true: accumulate region sums (conv2).
template <bool REGION>
__global__ void __launch_bounds__(128)
edge_kernel(const int* __restrict__ src, const float* __restrict__ W2,
            const float* __restrict__ b2, const int* __restrict__ labels) {
    __shared__ __align__(16) float sh[4][HDIM];
    __shared__ float sq[RREG * HDIM];
    int tid = threadIdx.x, lane = tid & 31, wip = tid >> 5;
    if (REGION) {
        for (int j = tid; j < RREG * HDIM; j += 128) sq[j] = 0.f;
        __syncthreads();
    }
    // W2 columns in registers
    float w0[HDIM], w1[HDIM];
#pragma unroll
    for (int k = 0; k < HDIM; k++) {
        w0[k] = __ldg(W2 + k * HDIM + lane);
        w1[k] = __ldg(W2 + k * HDIM + 32 + lane);
    }
    float bb0 = __ldg(b2 + lane), bb1 = __ldg(b2 + 32 + lane);
    float* shp = sh[wip];
    const float NEGINF = __int_as_float(0xff800000);
    int gw = (blockIdx.x * 128 + tid) >> 5;
    int nw = gridDim.x * 4;

    for (int i = gw; i < NN; i += nw) {
        float2 av = __ldg(((const float2*)g_A) + i * 32 + lane);
        int sv = __ldg(src + i * DEG + (lane & 15));   // 16 srcs in lanes 0..15
        float acc0 = NEGINF, acc1 = NEGINF;
        // software pipeline the gather
        int s0i = __shfl_sync(0xffffffffu, sv, 0);
        float2 bv = __ldg(((const float2*)g_B) + s0i * 32 + lane);
#pragma unroll 1
        for (int e = 0; e < DEG; e++) {
            float h0 = fmaxf(av.x + bv.x, 0.f);
            float h1 = fmaxf(av.y + bv.y, 0.f);
            __syncwarp();
            ((float2*)shp)[lane] = make_float2(h0, h1);
            __syncwarp();
            if (e + 1 < DEG) {
                int sn = __shfl_sync(0xffffffffu, sv, e + 1);
                bv = __ldg(((const float2*)g_B) + sn * 32 + lane);
            }
            float s0 = 0.f, s1 = 0.f;
#pragma unroll
            for (int k4 = 0; k4 < HDIM / 4; k4++) {
                float4 hv = ((const float4*)shp)[k4];
                s0 = fmaf(hv.x, w0[4 * k4 + 0], s0); s1 = fmaf(hv.x, w1[4 * k4 + 0], s1);
                s0 = fmaf(hv.y, w0[4 * k4 + 1], s0); s1 = fmaf(hv.y, w1[4 * k4 + 1], s1);
                s0 = fmaf(hv.z, w0[4 * k4 + 2], s0); s1 = fmaf(hv.z, w1[4 * k4 + 2], s1);
                s0 = fmaf(hv.w, w0[4 * k4 + 3], s0); s1 = fmaf(hv.w, w1[4 * k4 + 3], s1);
            }
            acc0 = fmaxf(acc0, s0);
            acc1 = fmaxf(acc1, s1);
        }
        float o0 = fmaxf(acc0 + bb0, 0.f);
        float o1 = fmaxf(acc1 + bb1, 0.f);
        if (!REGION) {
            g_h[i * HDIM + lane] = o0;
            g_h[i * HDIM + 32 + lane] = o1;
        } else {
            int lab = __ldg(labels + i);
            atomicAdd(&sq[lab * HDIM + lane], o0);
            atomicAdd(&sq[lab * HDIM + 32 + lane], o1);
        }
    }
    if (REGION) {
        __syncthreads();
        for (int j = tid; j < RREG * HDIM; j += 128) atomicAdd(&g_qsum[j], sq[j]);
    }
}

// Quotient graph (8 nodes, ~32 edges) + pooling + final linear. One block, 64 threads.
__global__ void tail_kernel(const int* __restrict__ qe, int Eq,
                            const float* __restrict__ W31, const float* __restrict__ b31,
                            const float* __restrict__ W32, const float* __restrict__ b32,
                            const float* __restrict__ W41, const float* __restrict__ b41,
                            const float* __restrict__ W42, const float* __restrict__ b42,
                            const float* __restrict__ linW, const float* __restrict__ linb,
                            float* __restrict__ out) {
    __shared__ float q[RREG][HDIM], Aa[RREG][HDIM], Bb[RREG][HDIM], m[RREG][HDIM];
    __shared__ float semb[HDIM];
    int c = threadIdx.x;
    const float NEGINF = __int_as_float(0xff800000);

    for (int r = 0; r < RREG; r++) {
        float cnt = (float)g_qcnt[r];
        q[r][c] = g_qsum[r * HDIM + c] / fmaxf(cnt, 1.f);
    }
    __syncthreads();

    for (int layer = 0; layer < 2; layer++) {
        const float* W1  = layer ? W41 : W31;
        const float* b1v = layer ? b41 : b31;
        const float* W2  = layer ? W42 : W32;
        const float* b2v = layer ? b42 : b32;
        // node transform
        for (int r = 0; r < RREG; r++) {
            float a = 0.f, b = 0.f;
#pragma unroll 8
            for (int k = 0; k < HDIM; k++) {
                float f = q[r][k];
                float wa = __ldg(W1 + k * HDIM + c);
                float wb = __ldg(W1 + (k + HDIM) * HDIM + c);
                a = fmaf(f, wa - wb, a);
                b = fmaf(f, wb, b);
            }
            Aa[r][c] = a + __ldg(b1v + c);
            Bb[r][c] = b;
            m[r][c] = NEGINF;
        }
        __syncthreads();
        // edges
        for (int e = 0; e < Eq; e++) {
            int s = __ldg(qe + e);
            int t = __ldg(qe + Eq + e);
            float acc = 0.f;
#pragma unroll 8
            for (int k = 0; k < HDIM; k++) {
                float hk = fmaxf(Aa[t][k] + Bb[s][k], 0.f);
                acc = fmaf(hk, __ldg(W2 + k * HDIM + c), acc);
            }
            m[t][c] = fmaxf(m[t][c], acc);
        }
        __syncthreads();
        for (int r = 0; r < RREG; r++) {
            float v = m[r][c];
            v = (v == NEGINF) ? 0.f : (v + __ldg(b2v + c));
            q[r][c] = fmaxf(v, 0.f);
        }
        __syncthreads();
    }
    // global add pool + linear
    float emb = 0.f;
    for (int r = 0; r < RREG; r++) emb += q[r][c];
    semb[c] = emb;
    __syncthreads();
    if (c < 8) {
        float o = __ldg(linb + c);
#pragma unroll 8
        for (int k = 0; k < HDIM; k++) o = fmaf(semb[k], __ldg(linW + k * 8 + c), o);
        out[c] = o;
    }
}

// ---------------------------------------------------------------------
extern "C" void kernel_launch(void* const* d_in, const int* in_sizes, int n_in,
                              void* d_out, int out_size) {
    const float* x      = (const float*)d_in[0];
    const float* pos    = (const float*)d_in[1];
    const int*   ei     = (const int*)d_in[2];
    const int*   labels = (const int*)d_in[3];
    const int*   qe     = (const int*)d_in[4];
    const float* W11 = (const float*)d_in[5],  *b11 = (const float*)d_in[6];
    const float* W12 = (const float*)d_in[7],  *b12 = (const float*)d_in[8];
    const float* W21 = (const float*)d_in[9],  *b21 = (const float*)d_in[10];
    const float* W22 = (const float*)d_in[11], *b22 = (const float*)d_in[12];
    const float* W31 = (const float*)d_in[13], *b31 = (const float*)d_in[14];
    const float* W32 = (const float*)d_in[15], *b32 = (const float*)d_in[16];
    const float* W41 = (const float*)d_in[17], *b41 = (const float*)d_in[18];
    const float* W42 = (const float*)d_in[19], *b42 = (const float*)d_in[20];
    const float* linW = (const float*)d_in[21], *linb = (const float*)d_in[22];

    int Eq = in_sizes[4] / 2;       // quotient edges (32)
    const int* src = ei;            // edge_index row 0 = src; row 1 (tgt) is repeat(arange(N),16)

    init_kernel<<<1, 512>>>();
    count_kernel<<<256, 256>>>(labels);
    node1_kernel<<<1480, 256>>>(x, pos, W11, b11);
    edge_kernel<false><<<888, 128>>>(src, W12, b12, nullptr);
    node2_kernel<<<1480, 256>>>(W21, b21);
    edge_kernel<true><<<888, 128>>>(src, W22, b22, labels);
    tail_kernel<<<1, 64>>>(qe, Eq, W31, b31, W32, b32, W41, b41, W42, b42,
                           linW, linb, (float*)d_out);
}

// round 3
// speedup vs baseline: 1.6107x; 1.6107x over previous
#include <cuda_runtime.h>
#include <cstdint>
#include <math.h>

#define NN    100000
#define DEG   16
#define FDIM  16
#define PDIM  3
#define HDIM  64
#define RREG  8
#define DIN1  19

// -------- scratch (no allocations allowed; static device globals) --------
__device__ float g_A[NN * HDIM];      // per-node "center" term
__device__ float g_B[NN * HDIM];      // per-node "neighbor" term
__device__ float g_h[NN * HDIM];      // conv1 output
__device__ float g_qsum[RREG * HDIM]; // region feature sums
__device__ int   g_qcnt[RREG];        // region counts

__device__ __forceinline__ uint32_t f2tf(float f) {
    uint32_t r;
    asm("cvt.rna.tf32.f32 %0, %1;" : "=r"(r) : "f"(f));
    return r;
}

// m16n8k8 tf32 mma (baseline PTX, valid on compute_103)
__device__ __forceinline__ void mma_tf32(float& c0, float& c1, float& c2, float& c3,
                                         uint32_t a0, uint32_t a1, uint32_t a2, uint32_t a3,
                                         uint32_t b0, uint32_t b1) {
    asm volatile("mma.sync.aligned.m16n8k8.row.col.f32.tf32.tf32.f32 "
                 "{%0,%1,%2,%3}, {%4,%5,%6,%7}, {%8,%9}, {%0,%1,%2,%3};"
                 : "+f"(c0), "+f"(c1), "+f"(c2), "+f"(c3)
                 : "r"(a0), "r"(a1), "r"(a2), "r"(a3), "r"(b0), "r"(b1));
}

// ---------------------------------------------------------------------
__global__ void init_kernel() {
    int t = threadIdx.x;
    if (t < RREG * HDIM) g_qsum[t] = 0.f;
    if (t < RREG)        g_qcnt[t] = 0;
}

__global__ void count_kernel(const int* __restrict__ labels) {
    __shared__ int hist[RREG];
    if (threadIdx.x < RREG) hist[threadIdx.x] = 0;
    __syncthreads();
    int stride = gridDim.x * blockDim.x;
    for (int i = blockIdx.x * blockDim.x + threadIdx.x; i < NN; i += stride)
        atomicAdd(&hist[labels[i]], 1);
    __syncthreads();
    if (threadIdx.x < RREG) atomicAdd(&g_qcnt[threadIdx.x], hist[threadIdx.x]);
}

// conv1 node transform: f = [x, pos] (19 dims), fp32 SIMT (K too small for mma)
__global__ void node1_kernel(const float* __restrict__ x, const float* __restrict__ pos,
                             const float* __restrict__ W1, const float* __restrict__ b1) {
    __shared__ float sW[2 * DIN1 * HDIM];
    for (int j = threadIdx.x; j < DIN1 * HDIM; j += blockDim.x) {
        float wb = W1[j + DIN1 * HDIM];
        sW[j] = W1[j] - wb;
        sW[j + DIN1 * HDIM] = wb;
    }
    __syncthreads();
    int stride = gridDim.x * blockDim.x;
    for (int idx = blockIdx.x * blockDim.x + threadIdx.x; idx < NN * HDIM; idx += stride) {
        int i = idx >> 6;
        int c = idx & 63;
        float a = 0.f, b = 0.f;
#pragma unroll
        for (int k = 0; k < DIN1; k++) {
            float f = (k < FDIM) ? __ldg(x + i * FDIM + k)
                                 : __ldg(pos + i * PDIM + (k - FDIM));
            a = fmaf(f, sW[k * HDIM + c], a);
            b = fmaf(f, sW[(k + DIN1) * HDIM + c], b);
        }
        g_A[idx] = a + __ldg(b1 + c);
        g_B[idx] = b;
    }
}

// ============ node2: g_A/g_B = g_h @ [W1a-W1b | W1b] via mma (tf32) ============
// warp-tile = 16 rows x 128 cols. acc[16 ntiles][4]. K split in halves of 32.
__global__ void __launch_bounds__(128, 4)
node2_mma_kernel(const float* __restrict__ W1, const float* __restrict__ b1) {
    __shared__ uint32_t sWf[8192];       // [ki(8)][ni(16)][reg(2)][lane(32)] 32KB
    __shared__ uint32_t sH[4][16 * 36];  // per-warp staging, pad stride 36
    const int tid = threadIdx.x, lane = tid & 31, w = tid >> 5;
    const int g = lane >> 2, cp = lane & 3;

    for (int idx = tid; idx < 8192; idx += 128) {
        int l = idx & 31, reg = (idx >> 5) & 1, ni = (idx >> 6) & 15, ki = idx >> 10;
        int k = ki * 8 + (l & 3) + reg * 4;
        int n = ni * 8 + (l >> 2);
        float v;
        if (n < 64) v = __ldg(W1 + k * 64 + n) - __ldg(W1 + (k + 64) * 64 + n);
        else        v = __ldg(W1 + (k + 64) * 64 + (n - 64));
        sWf[idx] = f2tf(v);
    }
    __syncthreads();

    uint32_t* sHw = sH[w];
    const int nwarp = gridDim.x * 4;
    for (int tile = blockIdx.x * 4 + w; tile < NN / 16; tile += nwarp) {
        const int row0 = tile * 16;
        float acc[16][4];
#pragma unroll
        for (int ni = 0; ni < 16; ni++)
#pragma unroll
            for (int r = 0; r < 4; r++) acc[ni][r] = 0.f;

#pragma unroll
        for (int kh = 0; kh < 2; kh++) {
            const float4* hp = (const float4*)(g_h + (row0 + (lane >> 1)) * 64 + kh * 32 + (lane & 1) * 16);
            __syncwarp();
#pragma unroll
            for (int j = 0; j < 4; j++) {
                float4 v = __ldg(hp + j);
                uint32_t* p = sHw + (lane >> 1) * 36 + (lane & 1) * 16 + j * 4;
                p[0] = f2tf(v.x); p[1] = f2tf(v.y); p[2] = f2tf(v.z); p[3] = f2tf(v.w);
            }
            __syncwarp();
#pragma unroll
            for (int kL = 0; kL < 4; kL++) {
                const uint32_t* r0 = sHw + g * 36 + kL * 8 + cp;
                uint32_t a0 = r0[0], a1 = r0[8 * 36], a2 = r0[4], a3 = r0[8 * 36 + 4];
                const uint32_t* bp = sWf + (kh * 4 + kL) * 1024 + lane;
#pragma unroll
                for (int ni = 0; ni < 16; ni++) {
                    uint32_t b0 = bp[ni * 64], b1v = bp[ni * 64 + 32];
                    mma_tf32(acc[ni][0], acc[ni][1], acc[ni][2], acc[ni][3],
                             a0, a1, a2, a3, b0, b1v);
                }
            }
        }
        // epilogue: c0/c1 at (row0+g, col..col+1), c2/c3 at (row0+g+8, ...)
#pragma unroll
        for (int ni = 0; ni < 16; ni++) {
            int col = (ni & 7) * 8 + 2 * cp;
            float ax = 0.f, ay = 0.f;
            float* dst;
            if (ni < 8) {
                float2 bb = *(const float2*)(b1 + col);
                ax = bb.x; ay = bb.y;
                dst = g_A;
            } else {
                dst = g_B;
            }
            *(float2*)(dst + (row0 + g) * 64 + col)     = make_float2(acc[ni][0] + ax, acc[ni][1] + ay);
            *(float2*)(dst + (row0 + g + 8) * 64 + col) = make_float2(acc[ni][2] + ax, acc[ni][3] + ay);
        }
    }
}

// ============ edge conv via mma: warp-tile = 32 edge-rows = 2 nodes ============
// D(32x64) = relu(A_tgt + B_src)(32x64) @ W2(64x64); segment-max over 16-row groups.
template <bool REGION>
__global__ void __launch_bounds__(128, 4)
edge_mma_kernel(const int* __restrict__ src, const float* __restrict__ W2,
                const float* __restrict__ b2, const int* __restrict__ labels) {
    __shared__ uint32_t sWf[4096];       // [ki(8)][ni(8)][reg(2)][lane(32)] 16KB
    __shared__ uint32_t sH[4][32 * 36];  // per-warp 32 rows x 32 k (half), pad 36
    __shared__ float sq[REGION ? 4 * RREG * HDIM : 1];

    const int tid = threadIdx.x, lane = tid & 31, w = tid >> 5;
    const int g = lane >> 2, cp = lane & 3;

    if (REGION)
        for (int j = tid; j < 4 * RREG * HDIM; j += 128) sq[j] = 0.f;

    for (int idx = tid; idx < 4096; idx += 128) {
        int l = idx & 31, reg = (idx >> 5) & 1, ni = (idx >> 6) & 7, ki = idx >> 9;
        int k = ki * 8 + (l & 3) + reg * 4;
        int n = ni * 8 + (l >> 2);
        sWf[idx] = f2tf(__ldg(W2 + k * 64 + n));
    }
    __syncthreads();

    uint32_t* sHw = sH[w];
    const int nwarp = gridDim.x * 4;
    for (int tile = blockIdx.x * 4 + w; tile < NN / 2; tile += nwarp) {
        const int n0 = tile * 2;
        const int node = n0 + (lane >> 4);               // rows 0-15 -> node0, 16-31 -> node1
        const int s = __ldg(src + tile * 32 + lane);     // edges contiguous (tgt = repeat)
        float acc[2][8][4];
#pragma unroll
        for (int mi = 0; mi < 2; mi++)
#pragma unroll
            for (int ni = 0; ni < 8; ni++)
#pragma unroll
                for (int r = 0; r < 4; r++) acc[mi][ni][r] = 0.f;

#pragma unroll
        for (int kh = 0; kh < 2; kh++) {
            const float4* Ap = (const float4*)(g_A + node * 64 + kh * 32);
            const float4* Bp = (const float4*)(g_B + s * 64 + kh * 32);
            __syncwarp();
#pragma unroll
            for (int j = 0; j < 8; j++) {
                float4 a4 = __ldg(Ap + j);
                float4 b4 = __ldg(Bp + j);
                uint32_t* p = sHw + lane * 36 + j * 4;
                p[0] = f2tf(fmaxf(a4.x + b4.x, 0.f));
                p[1] = f2tf(fmaxf(a4.y + b4.y, 0.f));
                p[2] = f2tf(fmaxf(a4.z + b4.z, 0.f));
                p[3] = f2tf(fmaxf(a4.w + b4.w, 0.f));
            }
            __syncwarp();
#pragma unroll
            for (int kL = 0; kL < 4; kL++) {
                uint32_t a[2][4];
#pragma unroll
                for (int mi = 0; mi < 2; mi++) {
                    const uint32_t* r0 = sHw + (mi * 16 + g) * 36 + kL * 8 + cp;
                    a[mi][0] = r0[0];
                    a[mi][1] = r0[8 * 36];
                    a[mi][2] = r0[4];
                    a[mi][3] = r0[8 * 36 + 4];
                }
                const uint32_t* bp = sWf + (kh * 4 + kL) * 512 + lane;
#pragma unroll
                for (int ni = 0; ni < 8; ni++) {
                    uint32_t b0 = bp[ni * 64], b1v = bp[ni * 64 + 32];
                    mma_tf32(acc[0][ni][0], acc[0][ni][1], acc[0][ni][2], acc[0][ni][3],
                             a[0][0], a[0][1], a[0][2], a[0][3], b0, b1v);
                    mma_tf32(acc[1][ni][0], acc[1][ni][1], acc[1][ni][2], acc[1][ni][3],
                             a[1][0], a[1][1], a[1][2], a[1][3], b0, b1v);
                }
            }
        }
        // segment-max over the 16 rows of each m-tile
        float rr[2][8][2];
#pragma unroll
        for (int mi = 0; mi < 2; mi++)
#pragma unroll
            for (int ni = 0; ni < 8; ni++) {
                float v0 = fmaxf(acc[mi][ni][0], acc[mi][ni][2]);
                float v1 = fmaxf(acc[mi][ni][1], acc[mi][ni][3]);
                v0 = fmaxf(v0, __shfl_xor_sync(0xffffffffu, v0, 4));
                v1 = fmaxf(v1, __shfl_xor_sync(0xffffffffu, v1, 4));
                v0 = fmaxf(v0, __shfl_xor_sync(0xffffffffu, v0, 8));
                v1 = fmaxf(v1, __shfl_xor_sync(0xffffffffu, v1, 8));
                v0 = fmaxf(v0, __shfl_xor_sync(0xffffffffu, v0, 16));
                v1 = fmaxf(v1, __shfl_xor_sync(0xffffffffu, v1, 16));
                rr[mi][ni][0] = v0;
                rr[mi][ni][1] = v1;
            }
        if (!REGION) {
#pragma unroll
            for (int mi = 0; mi < 2; mi++)
#pragma unroll
                for (int nl = 0; nl < 4; nl++)
                    if (g == mi * 4 + nl) {
                        float2 bv0 = *(const float2*)(b2 + nl * 8 + 2 * cp);
                        float2 bv1 = *(const float2*)(b2 + (nl + 4) * 8 + 2 * cp);
                        *(float2*)(g_h + (n0 + mi) * 64 + nl * 8 + 2 * cp) =
                            make_float2(fmaxf(rr[mi][nl][0] + bv0.x, 0.f),
                                        fmaxf(rr[mi][nl][1] + bv0.y, 0.f));
                        *(float2*)(g_h + (n0 + mi) * 64 + (nl + 4) * 8 + 2 * cp) =
                            make_float2(fmaxf(rr[mi][nl + 4][0] + bv1.x, 0.f),
                                        fmaxf(rr[mi][nl + 4][1] + bv1.y, 0.f));
                    }
        } else {
#pragma unroll
            for (int mi = 0; mi < 2; mi++) {
#pragma unroll
                for (int nl = 0; nl < 4; nl++)
                    if (g == mi * 4 + nl) {
                        int lab = __ldg(labels + n0 + mi);
                        float* q = sq + w * (RREG * HDIM) + lab * HDIM;
                        float2 bv0 = *(const float2*)(b2 + nl * 8 + 2 * cp);
                        float2 bv1 = *(const float2*)(b2 + (nl + 4) * 8 + 2 * cp);
                        q[nl * 8 + 2 * cp]           += fmaxf(rr[mi][nl][0] + bv0.x, 0.f);
                        q[nl * 8 + 2 * cp + 1]       += fmaxf(rr[mi][nl][1] + bv0.y, 0.f);
                        q[(nl + 4) * 8 + 2 * cp]     += fmaxf(rr[mi][nl + 4][0] + bv1.x, 0.f);
                        q[(nl + 4) * 8 + 2 * cp + 1] += fmaxf(rr[mi][nl + 4][1] + bv1.y, 0.f);
                    }
                __syncwarp();   // order mi=0 / mi=1 RMW groups (lab0 may equal lab1)
            }
        }
    }

    if (REGION) {
        __syncthreads();
        for (int j = tid; j < RREG * HDIM; j += 128) {
            float v = sq[j] + sq[RREG * HDIM + j] + sq[2 * RREG * HDIM + j] + sq[3 * RREG * HDIM + j];
            atomicAdd(&g_qsum[j], v);
        }
    }
}

// Quotient graph (8 nodes, ~32 edges) + pooling + final linear. One block, 64 threads.
__global__ void tail_kernel(const int* __restrict__ qe, int Eq,
                            const float* __restrict__ W31, const float* __restrict__ b31,
                            const float* __restrict__ W32, const float* __restrict__ b32,
                            const float* __restrict__ W41, const float* __restrict__ b41,
                            const float* __restrict__ W42, const float* __restrict__ b42,
                            const float* __restrict__ linW, const float* __restrict__ linb,
                            float* __restrict__ out) {
    __shared__ float q[RREG][HDIM], Aa[RREG][HDIM], Bb[RREG][HDIM], m[RREG][HDIM];
    __shared__ float semb[HDIM];
    int c = threadIdx.x;
    const float NEGINF = __int_as_float(0xff800000);

    for (int r = 0; r < RREG; r++) {
        float cnt = (float)g_qcnt[r];
        q[r][c] = g_qsum[r * HDIM + c] / fmaxf(cnt, 1.f);
    }
    __syncthreads();

    for (int layer = 0; layer < 2; layer++) {
        const float* W1  = layer ? W41 : W31;
        const float* b1v = layer ? b41 : b31;
        const float* W2  = layer ? W42 : W32;
        const float* b2v = layer ? b42 : b32;
        for (int r = 0; r < RREG; r++) {
            float a = 0.f, b = 0.f;
#pragma unroll 8
            for (int k = 0; k < HDIM; k++) {
                float f = q[r][k];
                float wa = __ldg(W1 + k * HDIM + c);
                float wb = __ldg(W1 + (k + HDIM) * HDIM + c);
                a = fmaf(f, wa - wb, a);
                b = fmaf(f, wb, b);
            }
            Aa[r][c] = a + __ldg(b1v + c);
            Bb[r][c] = b;
            m[r][c] = NEGINF;
        }
        __syncthreads();
        for (int e = 0; e < Eq; e++) {
            int s = __ldg(qe + e);
            int t = __ldg(qe + Eq + e);
            float acc = 0.f;
#pragma unroll 8
            for (int k = 0; k < HDIM; k++) {
                float hk = fmaxf(Aa[t][k] + Bb[s][k], 0.f);
                acc = fmaf(hk, __ldg(W2 + k * HDIM + c), acc);
            }
            m[t][c] = fmaxf(m[t][c], acc);
        }
        __syncthreads();
        for (int r = 0; r < RREG; r++) {
            float v = m[r][c];
            v = (v == NEGINF) ? 0.f : (v + __ldg(b2v + c));
            q[r][c] = fmaxf(v, 0.f);
        }
        __syncthreads();
    }
    float emb = 0.f;
    for (int r = 0; r < RREG; r++) emb += q[r][c];
    semb[c] = emb;
    __syncthreads();
    if (c < 8) {
        float o = __ldg(linb + c);
#pragma unroll 8
        for (int k = 0; k < HDIM; k++) o = fmaf(semb[k], __ldg(linW + k * 8 + c), o);
        out[c] = o;
    }
}

// ---------------------------------------------------------------------
extern "C" void kernel_launch(void* const* d_in, const int* in_sizes, int n_in,
                              void* d_out, int out_size) {
    const float* x      = (const float*)d_in[0];
    const float* pos    = (const float*)d_in[1];
    const int*   ei     = (const int*)d_in[2];
    const int*   labels = (const int*)d_in[3];
    const int*   qe     = (const int*)d_in[4];
    const float* W11 = (const float*)d_in[5],  *b11 = (const float*)d_in[6];
    const float* W12 = (const float*)d_in[7],  *b12 = (const float*)d_in[8];
    const float* W21 = (const float*)d_in[9],  *b21 = (const float*)d_in[10];
    const float* W22 = (const float*)d_in[11], *b22 = (const float*)d_in[12];
    const float* W31 = (const float*)d_in[13], *b31 = (const float*)d_in[14];
    const float* W32 = (const float*)d_in[15], *b32 = (const float*)d_in[16];
    const float* W41 = (const float*)d_in[17], *b41 = (const float*)d_in[18];
    const float* W42 = (const float*)d_in[19], *b42 = (const float*)d_in[20];
    const float* linW = (const float*)d_in[21], *linb = (const float*)d_in[22];

    int Eq = in_sizes[4] / 2;
    const int* src = ei;   // row 0 = src; row 1 (tgt) = repeat(arange(N),16)

    init_kernel<<<1, 512>>>();
    count_kernel<<<256, 256>>>(labels);
    node1_kernel<<<1480, 256>>>(x, pos, W11, b11);
    edge_mma_kernel<false><<<1184, 128>>>(src, W12, b12, nullptr);
    node2_mma_kernel<<<1184, 128>>>(W21, b21);
    edge_mma_kernel<true><<<1184, 128>>>(src, W22, b22, labels);
    tail_kernel<<<1, 64>>>(qe, Eq, W31, b31, W32, b32, W41, b41, W42, b42,
                           linW, linb, (float*)d_out);
}

// round 4
// speedup vs baseline: 1.9044x; 1.1824x over previous
#include <cuda_runtime.h>
#include <cstdint>
#include <math.h>

#define NN    100000
#define DEG   16
#define FDIM  16
#define PDIM  3
#define HDIM  64
#define RREG  8
#define DIN1  19

// -------- scratch (no allocations allowed; static device globals) --------
__device__ float g_A[NN * HDIM];      // per-node "center" term
__device__ float g_B[NN * HDIM];      // per-node "neighbor" term
__device__ float g_h[NN * HDIM];      // conv1 output
__device__ float g_qsum[RREG * HDIM]; // region feature sums
__device__ int   g_qcnt[RREG];        // region counts

__device__ __forceinline__ uint32_t f2tf(float f) {
    uint32_t r;
    asm("cvt.rna.tf32.f32 %0, %1;" : "=r"(r) : "f"(f));
    return r;
}

// m16n8k8 tf32 mma (baseline PTX, valid on compute_103)
__device__ __forceinline__ void mma_tf32(float& c0, float& c1, float& c2, float& c3,
                                         uint32_t a0, uint32_t a1, uint32_t a2, uint32_t a3,
                                         uint32_t b0, uint32_t b1) {
    asm volatile("mma.sync.aligned.m16n8k8.row.col.f32.tf32.tf32.f32 "
                 "{%0,%1,%2,%3}, {%4,%5,%6,%7}, {%8,%9}, {%0,%1,%2,%3};"
                 : "+f"(c0), "+f"(c1), "+f"(c2), "+f"(c3)
                 : "r"(a0), "r"(a1), "r"(a2), "r"(a3), "r"(b0), "r"(b1));
}

// ---------------------------------------------------------------------
__global__ void init_kernel() {
    int t = threadIdx.x;
    if (t < RREG * HDIM) g_qsum[t] = 0.f;
    if (t < RREG)        g_qcnt[t] = 0;
}

__global__ void count_kernel(const int* __restrict__ labels) {
    __shared__ int hist[RREG];
    if (threadIdx.x < RREG) hist[threadIdx.x] = 0;
    __syncthreads();
    int stride = gridDim.x * blockDim.x;
    for (int i = blockIdx.x * blockDim.x + threadIdx.x; i < NN; i += stride)
        atomicAdd(&hist[labels[i]], 1);
    __syncthreads();
    if (threadIdx.x < RREG) atomicAdd(&g_qcnt[threadIdx.x], hist[threadIdx.x]);
}

// conv1 node transform: f = [x, pos] (19 dims), fp32 SIMT (K too small for mma)
__global__ void node1_kernel(const float* __restrict__ x, const float* __restrict__ pos,
                             const float* __restrict__ W1, const float* __restrict__ b1) {
    __shared__ float sW[2 * DIN1 * HDIM];
    for (int j = threadIdx.x; j < DIN1 * HDIM; j += blockDim.x) {
        float wb = W1[j + DIN1 * HDIM];
        sW[j] = W1[j] - wb;
        sW[j + DIN1 * HDIM] = wb;
    }
    __syncthreads();
    int stride = gridDim.x * blockDim.x;
    for (int idx = blockIdx.x * blockDim.x + threadIdx.x; idx < NN * HDIM; idx += stride) {
        int i = idx >> 6;
        int c = idx & 63;
        float a = 0.f, b = 0.f;
#pragma unroll
        for (int k = 0; k < DIN1; k++) {
            float f = (k < FDIM) ? __ldg(x + i * FDIM + k)
                                 : __ldg(pos + i * PDIM + (k - FDIM));
            a = fmaf(f, sW[k * HDIM + c], a);
            b = fmaf(f, sW[(k + DIN1) * HDIM + c], b);
        }
        g_A[idx] = a + __ldg(b1 + c);
        g_B[idx] = b;
    }
}

// ============ node2: g_A/g_B = g_h @ [W1a-W1b | W1b] via mma (tf32) ============
__global__ void __launch_bounds__(128, 4)
node2_mma_kernel(const float* __restrict__ W1, const float* __restrict__ b1) {
    __shared__ uint32_t sWf[8192];       // [ki(8)][ni(16)][reg(2)][lane(32)] 32KB
    __shared__ uint32_t sH[4][16 * 36];  // per-warp staging, pad stride 36
    const int tid = threadIdx.x, lane = tid & 31, w = tid >> 5;
    const int g = lane >> 2, cp = lane & 3;

    for (int idx = tid; idx < 8192; idx += 128) {
        int l = idx & 31, reg = (idx >> 5) & 1, ni = (idx >> 6) & 15, ki = idx >> 10;
        int k = ki * 8 + (l & 3) + reg * 4;
        int n = ni * 8 + (l >> 2);
        float v;
        if (n < 64) v = __ldg(W1 + k * 64 + n) - __ldg(W1 + (k + 64) * 64 + n);
        else        v = __ldg(W1 + (k + 64) * 64 + (n - 64));
        sWf[idx] = f2tf(v);
    }
    __syncthreads();

    uint32_t* sHw = sH[w];
    const int nwarp = gridDim.x * 4;
    for (int tile = blockIdx.x * 4 + w; tile < NN / 16; tile += nwarp) {
        const int row0 = tile * 16;
        float acc[16][4];
#pragma unroll
        for (int ni = 0; ni < 16; ni++)
#pragma unroll
            for (int r = 0; r < 4; r++) acc[ni][r] = 0.f;

#pragma unroll
        for (int kh = 0; kh < 2; kh++) {
            const float4* hp = (const float4*)(g_h + (row0 + (lane >> 1)) * 64 + kh * 32 + (lane & 1) * 16);
            __syncwarp();
#pragma unroll
            for (int j = 0; j < 4; j++) {
                float4 v = __ldg(hp + j);
                uint32_t* p = sHw + (lane >> 1) * 36 + (lane & 1) * 16 + j * 4;
                p[0] = f2tf(v.x); p[1] = f2tf(v.y); p[2] = f2tf(v.z); p[3] = f2tf(v.w);
            }
            __syncwarp();
#pragma unroll
            for (int kL = 0; kL < 4; kL++) {
                const uint32_t* r0 = sHw + g * 36 + kL * 8 + cp;
                uint32_t a0 = r0[0], a1 = r0[8 * 36], a2 = r0[4], a3 = r0[8 * 36 + 4];
                const uint32_t* bp = sWf + (kh * 4 + kL) * 1024 + lane;
#pragma unroll
                for (int ni = 0; ni < 16; ni++) {
                    uint32_t b0 = bp[ni * 64], b1v = bp[ni * 64 + 32];
                    mma_tf32(acc[ni][0], acc[ni][1], acc[ni][2], acc[ni][3],
                             a0, a1, a2, a3, b0, b1v);
                }
            }
        }
#pragma unroll
        for (int ni = 0; ni < 16; ni++) {
            int col = (ni & 7) * 8 + 2 * cp;
            float ax = 0.f, ay = 0.f;
            float* dst;
            if (ni < 8) {
                float2 bb = *(const float2*)(b1 + col);
                ax = bb.x; ay = bb.y;
                dst = g_A;
            } else {
                dst = g_B;
            }
            *(float2*)(dst + (row0 + g) * 64 + col)     = make_float2(acc[ni][0] + ax, acc[ni][1] + ay);
            *(float2*)(dst + (row0 + g + 8) * 64 + col) = make_float2(acc[ni][2] + ax, acc[ni][3] + ay);
        }
    }
}

// ============ edge conv v2: warp-tile = 16 rows = 1 node, W2 in registers ============
template <bool REGION>
__global__ void __launch_bounds__(128)
edge_mma_kernel(const int* __restrict__ src, const float* __restrict__ W2,
                const float* __restrict__ b2, const int* __restrict__ labels) {
    __shared__ __align__(16) uint32_t sH[4][16 * 68];   // stride 68 words/row
    __shared__ float sq[REGION ? 4 * RREG * HDIM : 4];

    const int tid = threadIdx.x, lane = tid & 31, w = tid >> 5;
    const int g = lane >> 2, cp = lane & 3;
    const int c = lane & 7, rsub = lane >> 3;

    if (REGION)
        for (int j = tid; j < 4 * RREG * HDIM; j += 128) sq[j] = 0.f;
    __syncthreads();

    // W2 fragments resident in registers (amortized over ~84 tiles/warp)
    uint32_t Wr[8][8][2];
#pragma unroll
    for (int ks = 0; ks < 8; ks++)
#pragma unroll
        for (int ni = 0; ni < 8; ni++) {
            Wr[ks][ni][0] = f2tf(__ldg(W2 + (ks * 8 + cp) * 64 + ni * 8 + g));
            Wr[ks][ni][1] = f2tf(__ldg(W2 + (ks * 8 + cp + 4) * 64 + ni * 8 + g));
        }
    const float bb0 = __ldg(b2 + 2 * lane);
    const float bb1 = __ldg(b2 + 2 * lane + 1);

    uint32_t* sHw = sH[w];
    float* sqw = sq + (REGION ? w * (RREG * HDIM) : 0);

    const int step = gridDim.x * 4;
    for (int tile = blockIdx.x * 4 + w; tile < NN; tile += step) {
        // 16 source indices for this node (lanes 16-31 mirror 0-15)
        const int sv = __ldg(src + tile * DEG + (lane & 15));
        // A row of this node, lane's chunks c and c+8
        const float4 av0 = __ldg((const float4*)(g_A + (size_t)tile * 64) + c);
        const float4 av1 = __ldg((const float4*)(g_A + (size_t)tile * 64) + c + 8);
        // coalesced gather: 4 rows per instruction (lanes 0-7 -> row q*4+0 chunks 0-7, ...)
        float4 bq0[4], bq1[4];
#pragma unroll
        for (int q = 0; q < 4; q++) {
            int r = q * 4 + rsub;
            int s = __shfl_sync(0xffffffffu, sv, r);
            const float4* bp = (const float4*)(g_B + (size_t)s * 64);
            bq0[q] = __ldg(bp + c);
            bq1[q] = __ldg(bp + c + 8);
        }
        // h = relu(A + B) -> tf32 -> staging
#pragma unroll
        for (int q = 0; q < 4; q++) {
            int r = q * 4 + rsub;
            uint4 h0, h1;
            h0.x = f2tf(fmaxf(av0.x + bq0[q].x, 0.f));
            h0.y = f2tf(fmaxf(av0.y + bq0[q].y, 0.f));
            h0.z = f2tf(fmaxf(av0.z + bq0[q].z, 0.f));
            h0.w = f2tf(fmaxf(av0.w + bq0[q].w, 0.f));
            h1.x = f2tf(fmaxf(av1.x + bq1[q].x, 0.f));
            h1.y = f2tf(fmaxf(av1.y + bq1[q].y, 0.f));
            h1.z = f2tf(fmaxf(av1.z + bq1[q].z, 0.f));
            h1.w = f2tf(fmaxf(av1.w + bq1[q].w, 0.f));
            *(uint4*)(sHw + r * 68 + c * 4) = h0;
            *(uint4*)(sHw + r * 68 + (c + 8) * 4) = h1;
        }
        __syncwarp();

        float acc[8][4] = {};
#pragma unroll
        for (int ks = 0; ks < 8; ks++) {
            const uint32_t* base = sHw + g * 68 + ks * 8 + cp;   // conflict-free
            uint32_t a0 = base[0], a1 = base[8 * 68], a2 = base[4], a3 = base[8 * 68 + 4];
#pragma unroll
            for (int ni = 0; ni < 8; ni++)
                mma_tf32(acc[ni][0], acc[ni][1], acc[ni][2], acc[ni][3],
                         a0, a1, a2, a3, Wr[ks][ni][0], Wr[ks][ni][1]);
        }
        __syncwarp();

        // segment-max over the 16 rows; lane ends up owning cols (2*lane, 2*lane+1)
        float vx = 0.f, vy = 0.f;
#pragma unroll
        for (int ni = 0; ni < 8; ni++) {
            float v0 = fmaxf(acc[ni][0], acc[ni][2]);
            float v1 = fmaxf(acc[ni][1], acc[ni][3]);
            v0 = fmaxf(v0, __shfl_xor_sync(0xffffffffu, v0, 4));
            v1 = fmaxf(v1, __shfl_xor_sync(0xffffffffu, v1, 4));
            v0 = fmaxf(v0, __shfl_xor_sync(0xffffffffu, v0, 8));
            v1 = fmaxf(v1, __shfl_xor_sync(0xffffffffu, v1, 8));
            v0 = fmaxf(v0, __shfl_xor_sync(0xffffffffu, v0, 16));
            v1 = fmaxf(v1, __shfl_xor_sync(0xffffffffu, v1, 16));
            if ((lane >> 2) == ni) { vx = v0; vy = v1; }
        }
        const float o0 = fmaxf(vx + bb0, 0.f);
        const float o1 = fmaxf(vy + bb1, 0.f);
        if (!REGION) {
            *(float2*)(g_h + (size_t)tile * 64 + 2 * lane) = make_float2(o0, o1);
        } else {
            const int lab = __ldg(labels + tile);
            float* p = sqw + lab * 64 + 2 * lane;
            float2 cur = *(float2*)p;
            *(float2*)p = make_float2(cur.x + o0, cur.y + o1);
        }
    }

    if (REGION) {
        __syncthreads();
        for (int j = tid; j < RREG * HDIM; j += 128)
            atomicAdd(&g_qsum[j],
                      sq[j] + sq[RREG * HDIM + j] + sq[2 * RREG * HDIM + j] + sq[3 * RREG * HDIM + j]);
    }
}

// Quotient graph (8 nodes, ~32 edges) + pooling + final linear. One block, 64 threads.
__global__ void tail_kernel(const int* __restrict__ qe, int Eq,
                            const float* __restrict__ W31, const float* __restrict__ b31,
                            const float* __restrict__ W32, const float* __restrict__ b32,
                            const float* __restrict__ W41, const float* __restrict__ b41,
                            const float* __restrict__ W42, const float* __restrict__ b42,
                            const float* __restrict__ linW, const float* __restrict__ linb,
                            float* __restrict__ out) {
    __shared__ float q[RREG][HDIM], Aa[RREG][HDIM], Bb[RREG][HDIM], m[RREG][HDIM];
    __shared__ float semb[HDIM];
    int c = threadIdx.x;
    const float NEGINF = __int_as_float(0xff800000);

    for (int r = 0; r < RREG; r++) {
        float cnt = (float)g_qcnt[r];
        q[r][c] = g_qsum[r * HDIM + c] / fmaxf(cnt, 1.f);
    }
    __syncthreads();

    for (int layer = 0; layer < 2; layer++) {
        const float* W1  = layer ? W41 : W31;
        const float* b1v = layer ? b41 : b31;
        const float* W2  = layer ? W42 : W32;
        const float* b2v = layer ? b42 : b32;
        for (int r = 0; r < RREG; r++) {
            float a = 0.f, b = 0.f;
#pragma unroll 8
            for (int k = 0; k < HDIM; k++) {
                float f = q[r][k];
                float wa = __ldg(W1 + k * HDIM + c);
                float wb = __ldg(W1 + (k + HDIM) * HDIM + c);
                a = fmaf(f, wa - wb, a);
                b = fmaf(f, wb, b);
            }
            Aa[r][c] = a + __ldg(b1v + c);
            Bb[r][c] = b;
            m[r][c] = NEGINF;
        }
        __syncthreads();
        for (int e = 0; e < Eq; e++) {
            int s = __ldg(qe + e);
            int t = __ldg(qe + Eq + e);
            float acc = 0.f;
#pragma unroll 8
            for (int k = 0; k < HDIM; k++) {
                float hk = fmaxf(Aa[t][k] + Bb[s][k], 0.f);
                acc = fmaf(hk, __ldg(W2 + k * HDIM + c), acc);
            }
            m[t][c] = fmaxf(m[t][c], acc);
        }
        __syncthreads();
        for (int r = 0; r < RREG; r++) {
            float v = m[r][c];
            v = (v == NEGINF) ? 0.f : (v + __ldg(b2v + c));
            q[r][c] = fmaxf(v, 0.f);
        }
        __syncthreads();
    }
    float emb = 0.f;
    for (int r = 0; r < RREG; r++) emb += q[r][c];
    semb[c] = emb;
    __syncthreads();
    if (c < 8) {
        float o = __ldg(linb + c);
#pragma unroll 8
        for (int k = 0; k < HDIM; k++) o = fmaf(semb[k], __ldg(linW + k * 8 + c), o);
        out[c] = o;
    }
}

// ---------------------------------------------------------------------
extern "C" void kernel_launch(void* const* d_in, const int* in_sizes, int n_in,
                              void* d_out, int out_size) {
    const float* x      = (const float*)d_in[0];
    const float* pos    = (const float*)d_in[1];
    const int*   ei     = (const int*)d_in[2];
    const int*   labels = (const int*)d_in[3];
    const int*   qe     = (const int*)d_in[4];
    const float* W11 = (const float*)d_in[5],  *b11 = (const float*)d_in[6];
    const float* W12 = (const float*)d_in[7],  *b12 = (const float*)d_in[8];
    const float* W21 = (const float*)d_in[9],  *b21 = (const float*)d_in[10];
    const float* W22 = (const float*)d_in[11], *b22 = (const float*)d_in[12];
    const float* W31 = (const float*)d_in[13], *b31 = (const float*)d_in[14];
    const float* W32 = (const float*)d_in[15], *b32 = (const float*)d_in[16];
    const float* W41 = (const float*)d_in[17], *b41 = (const float*)d_in[18];
    const float* W42 = (const float*)d_in[19], *b42 = (const float*)d_in[20];
    const float* linW = (const float*)d_in[21], *linb = (const float*)d_in[22];

    int Eq = in_sizes[4] / 2;
    const int* src = ei;   // row 0 = src; row 1 (tgt) = repeat(arange(N),16)

    init_kernel<<<1, 512>>>();
    count_kernel<<<256, 256>>>(labels);
    node1_kernel<<<1480, 256>>>(x, pos, W11, b11);
    edge_mma_kernel<false><<<296, 128>>>(src, W12, b12, nullptr);
    node2_mma_kernel<<<1184, 128>>>(W21, b21);
    edge_mma_kernel<true><<<296, 128>>>(src, W22, b22, labels);
    tail_kernel<<<1, 64>>>(qe, Eq, W31, b31, W32, b32, W41, b41, W42, b42,
                           linW, linb, (float*)d_out);
}

// round 5
// speedup vs baseline: 2.4318x; 1.2769x over previous
#include <cuda_runtime.h>
#include <cstdint>
#include <math.h>

#define NN    100000
#define DEG   16
#define FDIM  16
#define PDIM  3
#define HDIM  64
#define RREG  8
#define DIN1  19

// -------- scratch (no allocations allowed; static device globals) --------
__device__ float g_A[NN * HDIM];      // per-node "center" term
__device__ float g_B[NN * HDIM];      // per-node "neighbor" term
__device__ float g_h[NN * HDIM];      // conv1 output
__device__ float g_qsum[RREG * HDIM]; // region feature sums
__device__ int   g_qcnt[RREG];        // region counts

__device__ __forceinline__ uint32_t f2tf(float f) {
    uint32_t r;
    asm("cvt.rna.tf32.f32 %0, %1;" : "=r"(r) : "f"(f));
    return r;
}

// m16n8k8 tf32 mma (baseline PTX, valid on compute_103)
__device__ __forceinline__ void mma_tf32(float& c0, float& c1, float& c2, float& c3,
                                         uint32_t a0, uint32_t a1, uint32_t a2, uint32_t a3,
                                         uint32_t b0, uint32_t b1) {
    asm volatile("mma.sync.aligned.m16n8k8.row.col.f32.tf32.tf32.f32 "
                 "{%0,%1,%2,%3}, {%4,%5,%6,%7}, {%8,%9}, {%0,%1,%2,%3};"
                 : "+f"(c0), "+f"(c1), "+f"(c2), "+f"(c3)
                 : "r"(a0), "r"(a1), "r"(a2), "r"(a3), "r"(b0), "r"(b1));
}

// ---------------------------------------------------------------------
__global__ void init_kernel() {
    int t = threadIdx.x;
    if (t < RREG * HDIM) g_qsum[t] = 0.f;
    if (t < RREG)        g_qcnt[t] = 0;
}

__global__ void count_kernel(const int* __restrict__ labels) {
    __shared__ int hist[RREG];
    if (threadIdx.x < RREG) hist[threadIdx.x] = 0;
    __syncthreads();
    int stride = gridDim.x * blockDim.x;
    for (int i = blockIdx.x * blockDim.x + threadIdx.x; i < NN; i += stride)
        atomicAdd(&hist[labels[i]], 1);
    __syncthreads();
    if (threadIdx.x < RREG) atomicAdd(&g_qcnt[threadIdx.x], hist[threadIdx.x]);
}

// conv1 node transform: f = [x, pos] (19 dims), fp32 SIMT (K too small for mma)
__global__ void node1_kernel(const float* __restrict__ x, const float* __restrict__ pos,
                             const float* __restrict__ W1, const float* __restrict__ b1) {
    __shared__ float sW[2 * DIN1 * HDIM];
    for (int j = threadIdx.x; j < DIN1 * HDIM; j += blockDim.x) {
        float wb = W1[j + DIN1 * HDIM];
        sW[j] = W1[j] - wb;
        sW[j + DIN1 * HDIM] = wb;
    }
    __syncthreads();
    int stride = gridDim.x * blockDim.x;
    for (int idx = blockIdx.x * blockDim.x + threadIdx.x; idx < NN * HDIM; idx += stride) {
        int i = idx >> 6;
        int c = idx & 63;
        float a = 0.f, b = 0.f;
#pragma unroll
        for (int k = 0; k < DIN1; k++) {
            float f = (k < FDIM) ? __ldg(x + i * FDIM + k)
                                 : __ldg(pos + i * PDIM + (k - FDIM));
            a = fmaf(f, sW[k * HDIM + c], a);
            b = fmaf(f, sW[(k + DIN1) * HDIM + c], b);
        }
        g_A[idx] = a + __ldg(b1 + c);
        g_B[idx] = b;
    }
}

// ============ node2: g_A/g_B = g_h @ [W1a-W1b | W1b] via mma (tf32) ============
__global__ void __launch_bounds__(128, 4)
node2_mma_kernel(const float* __restrict__ W1, const float* __restrict__ b1) {
    __shared__ uint32_t sWf[8192];       // [ki(8)][ni(16)][reg(2)][lane(32)] 32KB
    __shared__ uint32_t sH[4][16 * 36];  // per-warp staging, pad stride 36
    const int tid = threadIdx.x, lane = tid & 31, w = tid >> 5;
    const int g = lane >> 2, cp = lane & 3;

    for (int idx = tid; idx < 8192; idx += 128) {
        int l = idx & 31, reg = (idx >> 5) & 1, ni = (idx >> 6) & 15, ki = idx >> 10;
        int k = ki * 8 + (l & 3) + reg * 4;
        int n = ni * 8 + (l >> 2);
        float v;
        if (n < 64) v = __ldg(W1 + k * 64 + n) - __ldg(W1 + (k + 64) * 64 + n);
        else        v = __ldg(W1 + (k + 64) * 64 + (n - 64));
        sWf[idx] = f2tf(v);
    }
    __syncthreads();

    uint32_t* sHw = sH[w];
    const int nwarp = gridDim.x * 4;
    for (int tile = blockIdx.x * 4 + w; tile < NN / 16; tile += nwarp) {
        const int row0 = tile * 16;
        float acc[16][4];
#pragma unroll
        for (int ni = 0; ni < 16; ni++)
#pragma unroll
            for (int r = 0; r < 4; r++) acc[ni][r] = 0.f;

#pragma unroll
        for (int kh = 0; kh < 2; kh++) {
            const float4* hp = (const float4*)(g_h + (row0 + (lane >> 1)) * 64 + kh * 32 + (lane & 1) * 16);
            __syncwarp();
#pragma unroll
            for (int j = 0; j < 4; j++) {
                float4 v = __ldg(hp + j);
                uint32_t* p = sHw + (lane >> 1) * 36 + (lane & 1) * 16 + j * 4;
                p[0] = f2tf(v.x); p[1] = f2tf(v.y); p[2] = f2tf(v.z); p[3] = f2tf(v.w);
            }
            __syncwarp();
#pragma unroll
            for (int kL = 0; kL < 4; kL++) {
                const uint32_t* r0 = sHw + g * 36 + kL * 8 + cp;
                uint32_t a0 = r0[0], a1 = r0[8 * 36], a2 = r0[4], a3 = r0[8 * 36 + 4];
                const uint32_t* bp = sWf + (kh * 4 + kL) * 1024 + lane;
#pragma unroll
                for (int ni = 0; ni < 16; ni++) {
                    uint32_t b0 = bp[ni * 64], b1v = bp[ni * 64 + 32];
                    mma_tf32(acc[ni][0], acc[ni][1], acc[ni][2], acc[ni][3],
                             a0, a1, a2, a3, b0, b1v);
                }
            }
        }
#pragma unroll
        for (int ni = 0; ni < 16; ni++) {
            int col = (ni & 7) * 8 + 2 * cp;
            float ax = 0.f, ay = 0.f;
            float* dst;
            if (ni < 8) {
                float2 bb = *(const float2*)(b1 + col);
                ax = bb.x; ay = bb.y;
                dst = g_A;
            } else {
                dst = g_B;
            }
            *(float2*)(dst + (row0 + g) * 64 + col)     = make_float2(acc[ni][0] + ax, acc[ni][1] + ay);
            *(float2*)(dst + (row0 + g + 8) * 64 + col) = make_float2(acc[ni][2] + ax, acc[ni][3] + ay);
        }
    }
}

// ============ edge conv v3: warp-tile = 1 node, W2 in regs, cross-tile pipeline ============
template <bool REGION>
__global__ void __launch_bounds__(128)
edge_mma_kernel(const int* __restrict__ src, const float* __restrict__ W2,
                const float* __restrict__ b2, const int* __restrict__ labels) {
    __shared__ __align__(16) uint32_t sH[4][16 * 68];   // stride 68 words/row
    __shared__ float sq[REGION ? 4 * RREG * HDIM : 4];

    const int tid = threadIdx.x, lane = tid & 31, w = tid >> 5;
    const int g = lane >> 2, cp = lane & 3;
    const int c = lane & 7, rsub = lane >> 3;

    if (REGION)
        for (int j = tid; j < 4 * RREG * HDIM; j += 128) sq[j] = 0.f;
    __syncthreads();

    // W2 fragments resident in registers (amortized over ~84 tiles/warp)
    uint32_t Wr[8][8][2];
#pragma unroll
    for (int ks = 0; ks < 8; ks++)
#pragma unroll
        for (int ni = 0; ni < 8; ni++) {
            Wr[ks][ni][0] = f2tf(__ldg(W2 + (ks * 8 + cp) * 64 + ni * 8 + g));
            Wr[ks][ni][1] = f2tf(__ldg(W2 + (ks * 8 + cp + 4) * 64 + ni * 8 + g));
        }
    const float bb0 = __ldg(b2 + 2 * lane);
    const float bb1 = __ldg(b2 + 2 * lane + 1);

    uint32_t* sHw = sH[w];
    float* sqw = sq + (REGION ? w * (RREG * HDIM) : 0);

    const int step = gridDim.x * 4;
    int cur = blockIdx.x * 4 + w;          // always < NN (1184 warps << 100K tiles)

    // ---- pipeline prologue: loads for 'cur', srcs for 'cur+step' ----
    int sv0 = __ldg(src + (size_t)cur * DEG + (lane & 15));
    int nx = cur + step; if (nx >= NN) nx = cur;
    int sv_n = __ldg(src + (size_t)nx * DEG + (lane & 15));
    float4 av0 = __ldg((const float4*)(g_A + (size_t)cur * 64) + c);
    float4 av1 = __ldg((const float4*)(g_A + (size_t)cur * 64) + c + 8);
    float4 bq0[4], bq1[4];
#pragma unroll
    for (int q = 0; q < 4; q++) {
        int s = __shfl_sync(0xffffffffu, sv0, q * 4 + rsub);
        const float4* bp = (const float4*)(g_B + (size_t)s * 64);
        bq0[q] = __ldg(bp + c);
        bq1[q] = __ldg(bp + c + 8);
    }

    while (true) {
        // ---- stage h(cur) = relu(A+B) -> tf32 (consumes av/bq) ----
#pragma unroll
        for (int q = 0; q < 4; q++) {
            int r = q * 4 + rsub;
            uint4 h0, h1;
            h0.x = f2tf(fmaxf(av0.x + bq0[q].x, 0.f));
            h0.y = f2tf(fmaxf(av0.y + bq0[q].y, 0.f));
            h0.z = f2tf(fmaxf(av0.z + bq0[q].z, 0.f));
            h0.w = f2tf(fmaxf(av0.w + bq0[q].w, 0.f));
            h1.x = f2tf(fmaxf(av1.x + bq1[q].x, 0.f));
            h1.y = f2tf(fmaxf(av1.y + bq1[q].y, 0.f));
            h1.z = f2tf(fmaxf(av1.z + bq1[q].z, 0.f));
            h1.w = f2tf(fmaxf(av1.w + bq1[q].w, 0.f));
            *(uint4*)(sHw + r * 68 + c * 4) = h0;
            *(uint4*)(sHw + r * 68 + (c + 8) * 4) = h1;
        }
        __syncwarp();

        // ---- prefetch tile nx (A, B) and srcs for nx+step; overlaps mma below ----
        int n2 = nx + step; if (n2 >= NN) n2 = nx;
        int sv_p = __ldg(src + (size_t)n2 * DEG + (lane & 15));
        av0 = __ldg((const float4*)(g_A + (size_t)nx * 64) + c);
        av1 = __ldg((const float4*)(g_A + (size_t)nx * 64) + c + 8);
#pragma unroll
        for (int q = 0; q < 4; q++) {
            int s = __shfl_sync(0xffffffffu, sv_n, q * 4 + rsub);
            const float4* bp = (const float4*)(g_B + (size_t)s * 64);
            bq0[q] = __ldg(bp + c);
            bq1[q] = __ldg(bp + c + 8);
        }

        // ---- mma on staged h(cur); independent of in-flight prefetch ----
        float acc[8][4] = {};
#pragma unroll
        for (int ks = 0; ks < 8; ks++) {
            const uint32_t* base = sHw + g * 68 + ks * 8 + cp;   // conflict-free
            uint32_t a0 = base[0], a1 = base[8 * 68], a2 = base[4], a3 = base[8 * 68 + 4];
#pragma unroll
            for (int ni = 0; ni < 8; ni++)
                mma_tf32(acc[ni][0], acc[ni][1], acc[ni][2], acc[ni][3],
                         a0, a1, a2, a3, Wr[ks][ni][0], Wr[ks][ni][1]);
        }
        __syncwarp();

        // ---- segment-max over 16 rows; lane owns cols (2*lane, 2*lane+1) ----
        float vx = 0.f, vy = 0.f;
#pragma unroll
        for (int ni = 0; ni < 8; ni++) {
            float v0 = fmaxf(acc[ni][0], acc[ni][2]);
            float v1 = fmaxf(acc[ni][1], acc[ni][3]);
            v0 = fmaxf(v0, __shfl_xor_sync(0xffffffffu, v0, 4));
            v1 = fmaxf(v1, __shfl_xor_sync(0xffffffffu, v1, 4));
            v0 = fmaxf(v0, __shfl_xor_sync(0xffffffffu, v0, 8));
            v1 = fmaxf(v1, __shfl_xor_sync(0xffffffffu, v1, 8));
            v0 = fmaxf(v0, __shfl_xor_sync(0xffffffffu, v0, 16));
            v1 = fmaxf(v1, __shfl_xor_sync(0xffffffffu, v1, 16));
            if ((lane >> 2) == ni) { vx = v0; vy = v1; }
        }
        const float o0 = fmaxf(vx + bb0, 0.f);
        const float o1 = fmaxf(vy + bb1, 0.f);
        if (!REGION) {
            *(float2*)(g_h + (size_t)cur * 64 + 2 * lane) = make_float2(o0, o1);
        } else {
            const int lab = __ldg(labels + cur);
            float* p = sqw + lab * 64 + 2 * lane;
            float2 t = *(float2*)p;
            *(float2*)p = make_float2(t.x + o0, t.y + o1);
        }

        // ---- rotate pipeline state ----
        int nc = cur + step;
        if (nc >= NN) break;
        cur = nc;
        nx = cur + step; if (nx >= NN) nx = cur;
        sv_n = sv_p;
    }

    if (REGION) {
        __syncthreads();
        for (int j = tid; j < RREG * HDIM; j += 128)
            atomicAdd(&g_qsum[j],
                      sq[j] + sq[RREG * HDIM + j] + sq[2 * RREG * HDIM + j] + sq[3 * RREG * HDIM + j]);
    }
}

// Quotient graph (8 nodes, ~32 edges) + pooling + final linear. One block, 64 threads.
__global__ void tail_kernel(const int* __restrict__ qe, int Eq,
                            const float* __restrict__ W31, const float* __restrict__ b31,
                            const float* __restrict__ W32, const float* __restrict__ b32,
                            const float* __restrict__ W41, const float* __restrict__ b41,
                            const float* __restrict__ W42, const float* __restrict__ b42,
                            const float* __restrict__ linW, const float* __restrict__ linb,
                            float* __restrict__ out) {
    __shared__ float q[RREG][HDIM], Aa[RREG][HDIM], Bb[RREG][HDIM], m[RREG][HDIM];
    __shared__ float semb[HDIM];
    int c = threadIdx.x;
    const float NEGINF = __int_as_float(0xff800000);

    for (int r = 0; r < RREG; r++) {
        float cnt = (float)g_qcnt[r];
        q[r][c] = g_qsum[r * HDIM + c] / fmaxf(cnt, 1.f);
    }
    __syncthreads();

    for (int layer = 0; layer < 2; layer++) {
        const float* W1  = layer ? W41 : W31;
        const float* b1v = layer ? b41 : b31;
        const float* W2  = layer ? W42 : W32;
        const float* b2v = layer ? b42 : b32;
        for (int r = 0; r < RREG; r++) {
            float a = 0.f, b = 0.f;
#pragma unroll 8
            for (int k = 0; k < HDIM; k++) {
                float f = q[r][k];
                float wa = __ldg(W1 + k * HDIM + c);
                float wb = __ldg(W1 + (k + HDIM) * HDIM + c);
                a = fmaf(f, wa - wb, a);
                b = fmaf(f, wb, b);
            }
            Aa[r][c] = a + __ldg(b1v + c);
            Bb[r][c] = b;
            m[r][c] = NEGINF;
        }
        __syncthreads();
        for (int e = 0; e < Eq; e++) {
            int s = __ldg(qe + e);
            int t = __ldg(qe + Eq + e);
            float acc = 0.f;
#pragma unroll 8
            for (int k = 0; k < HDIM; k++) {
                float hk = fmaxf(Aa[t][k] + Bb[s][k], 0.f);
                acc = fmaf(hk, __ldg(W2 + k * HDIM + c), acc);
            }
            m[t][c] = fmaxf(m[t][c], acc);
        }
        __syncthreads();
        for (int r = 0; r < RREG; r++) {
            float v = m[r][c];
            v = (v == NEGINF) ? 0.f : (v + __ldg(b2v + c));
            q[r][c] = fmaxf(v, 0.f);
        }
        __syncthreads();
    }
    float emb = 0.f;
    for (int r = 0; r < RREG; r++) emb += q[r][c];
    semb[c] = emb;
    __syncthreads();
    if (c < 8) {
        float o = __ldg(linb + c);
#pragma unroll 8
        for (int k = 0; k < HDIM; k++) o = fmaf(semb[k], __ldg(linW + k * 8 + c), o);
        out[c] = o;
    }
}

// ---------------------------------------------------------------------
extern "C" void kernel_launch(void* const* d_in, const int* in_sizes, int n_in,
                              void* d_out, int out_size) {
    const float* x      = (const float*)d_in[0];
    const float* pos    = (const float*)d_in[1];
    const int*   ei     = (const int*)d_in[2];
    const int*   labels = (const int*)d_in[3];
    const int*   qe     = (const int*)d_in[4];
    const float* W11 = (const float*)d_in[5],  *b11 = (const float*)d_in[6];
    const float* W12 = (const float*)d_in[7],  *b12 = (const float*)d_in[8];
    const float* W21 = (const float*)d_in[9],  *b21 = (const float*)d_in[10];
    const float* W22 = (const float*)d_in[11], *b22 = (const float*)d_in[12];
    const float* W31 = (const float*)d_in[13], *b31 = (const float*)d_in[14];
    const float* W32 = (const float*)d_in[15], *b32 = (const float*)d_in[16];
    const float* W41 = (const float*)d_in[17], *b41 = (const float*)d_in[18];
    const float* W42 = (const float*)d_in[19], *b42 = (const float*)d_in[20];
    const float* linW = (const float*)d_in[21], *linb = (const float*)d_in[22];

    int Eq = in_sizes[4] / 2;
    const int* src = ei;   // row 0 = src; row 1 (tgt) = repeat(arange(N),16)

    init_kernel<<<1, 512>>>();
    count_kernel<<<256, 256>>>(labels);
    node1_kernel<<<1480, 256>>>(x, pos, W11, b11);
    edge_mma_kernel<false><<<296, 128>>>(src, W12, b12, nullptr);
    node2_mma_kernel<<<1184, 128>>>(W21, b21);
    edge_mma_kernel<true><<<296, 128>>>(src, W22, b22, labels);
    tail_kernel<<<1, 64>>>(qe, Eq, W31, b31, W32, b32, W41, b41, W42, b42,
                           linW, linb, (float*)d_out);
}

// round 6
// speedup vs baseline: 3.2771x; 1.3476x over previous
#include <cuda_runtime.h>
#include <cstdint>
#include <math.h>

#define NN    100000
#define DEG   16
#define FDIM  16
#define PDIM  3
#define HDIM  64
#define RREG  8
#define DIN1  19

// -------- scratch (no allocations allowed; static device globals) --------
__device__ float g_A[NN * HDIM];      // per-node "center" term
__device__ float g_B[NN * HDIM];      // per-node "neighbor" term
__device__ float g_h[NN * HDIM];      // conv1 output
__device__ float g_qsum[RREG * HDIM]; // region feature sums
__device__ int   g_qcnt[RREG];        // region counts

__device__ __forceinline__ uint32_t f2tf(float f) {
    uint32_t r;
    asm("cvt.rna.tf32.f32 %0, %1;" : "=r"(r) : "f"(f));
    return r;
}

// m16n8k8 tf32 mma (baseline PTX, valid on compute_103)
__device__ __forceinline__ void mma_tf32(float& c0, float& c1, float& c2, float& c3,
                                         uint32_t a0, uint32_t a1, uint32_t a2, uint32_t a3,
                                         uint32_t b0, uint32_t b1) {
    asm volatile("mma.sync.aligned.m16n8k8.row.col.f32.tf32.tf32.f32 "
                 "{%0,%1,%2,%3}, {%4,%5,%6,%7}, {%8,%9}, {%0,%1,%2,%3};"
                 : "+f"(c0), "+f"(c1), "+f"(c2), "+f"(c3)
                 : "r"(a0), "r"(a1), "r"(a2), "r"(a3), "r"(b0), "r"(b1));
}

// ---------------------------------------------------------------------
__global__ void init_kernel() {
    int t = threadIdx.x;
    if (t < RREG * HDIM) g_qsum[t] = 0.f;
    if (t < RREG)        g_qcnt[t] = 0;
}

__global__ void count_kernel(const int* __restrict__ labels) {
    __shared__ int hist[RREG];
    if (threadIdx.x < RREG) hist[threadIdx.x] = 0;
    __syncthreads();
    int stride = gridDim.x * blockDim.x;
    for (int i = blockIdx.x * blockDim.x + threadIdx.x; i < NN; i += stride)
        atomicAdd(&hist[labels[i]], 1);
    __syncthreads();
    if (threadIdx.x < RREG) atomicAdd(&g_qcnt[threadIdx.x], hist[threadIdx.x]);
}

// ============ node1 v2: weights in registers, shfl broadcast, pipelined ============
// A[i] = f_i @ (W1a - W1b) + b1 ; B[i] = f_i @ W1b ; f = [x, pos] (19 dims)
__global__ void __launch_bounds__(128)
node1_kernel(const float* __restrict__ x, const float* __restrict__ pos,
             const float* __restrict__ W1, const float* __restrict__ b1) {
    const int tid = threadIdx.x, lane = tid & 31;
    // per-lane weight columns: c0 = lane, c1 = lane + 32
    float wA[DIN1][2], wB[DIN1][2];
#pragma unroll
    for (int k = 0; k < DIN1; k++) {
        float wb0 = __ldg(W1 + (k + DIN1) * HDIM + lane);
        float wb1 = __ldg(W1 + (k + DIN1) * HDIM + 32 + lane);
        wA[k][0] = __ldg(W1 + k * HDIM + lane) - wb0;
        wA[k][1] = __ldg(W1 + k * HDIM + 32 + lane) - wb1;
        wB[k][0] = wb0;
        wB[k][1] = wb1;
    }
    const float ba0 = __ldg(b1 + lane), ba1 = __ldg(b1 + 32 + lane);

    const int step = gridDim.x * 4;
    int i = blockIdx.x * 4 + (tid >> 5);
    if (i >= NN) return;

    float f = 0.f;
    if (lane < FDIM)            f = __ldg(x + (size_t)i * FDIM + lane);
    else if (lane < DIN1)       f = __ldg(pos + (size_t)i * PDIM + (lane - FDIM));

    while (true) {
        const int nx = i + step;
        float fn = 0.f;
        if (nx < NN) {
            if (lane < FDIM)      fn = __ldg(x + (size_t)nx * FDIM + lane);
            else if (lane < DIN1) fn = __ldg(pos + (size_t)nx * PDIM + (lane - FDIM));
        }
        float a0 = 0.f, a1 = 0.f, b0 = 0.f, b1v = 0.f;
#pragma unroll
        for (int k = 0; k < DIN1; k++) {
            const float fk = __shfl_sync(0xffffffffu, f, k);
            a0 = fmaf(fk, wA[k][0], a0);
            a1 = fmaf(fk, wA[k][1], a1);
            b0 = fmaf(fk, wB[k][0], b0);
            b1v = fmaf(fk, wB[k][1], b1v);
        }
        g_A[(size_t)i * 64 + lane]      = a0 + ba0;
        g_A[(size_t)i * 64 + 32 + lane] = a1 + ba1;
        g_B[(size_t)i * 64 + lane]      = b0;
        g_B[(size_t)i * 64 + 32 + lane] = b1v;
        if (nx >= NN) break;
        i = nx;
        f = fn;
    }
}

// ============ node2 v2: block tile of 16 rows, W-frags in regs (split over N by warp),
//              double-buffered shared staging, h prefetched one tile ahead ============
__global__ void __launch_bounds__(128)
node2_mma_kernel(const float* __restrict__ W1, const float* __restrict__ b1) {
    __shared__ __align__(16) uint32_t sH[2][16 * 68];
    const int tid = threadIdx.x, lane = tid & 31, w = tid >> 5;
    const int g = lane >> 2, cp = lane & 3;
    const int row = tid >> 3, cch = tid & 7;

    // warp w owns ni = w*4 + j (warps 0,1 -> A cols 0..63; warps 2,3 -> B cols)
    uint32_t Wr[8][4][2];
    float2 bias[4];
#pragma unroll
    for (int ks = 0; ks < 8; ks++)
#pragma unroll
        for (int j = 0; j < 4; j++) {
            const int ni = w * 4 + j;
            const int n = ni * 8 + g;
#pragma unroll
            for (int hh = 0; hh < 2; hh++) {
                const int k = ks * 8 + cp + hh * 4;
                float v;
                if (n < 64) v = __ldg(W1 + k * 64 + n) - __ldg(W1 + (k + 64) * 64 + n);
                else        v = __ldg(W1 + (k + 64) * 64 + (n - 64));
                Wr[ks][j][hh] = f2tf(v);
            }
        }
#pragma unroll
    for (int j = 0; j < 4; j++) {
        const int ni = w * 4 + j;
        const int col = (ni & 7) * 8 + 2 * cp;
        bias[j] = (ni < 8) ? *(const float2*)(b1 + col) : make_float2(0.f, 0.f);
    }

    const int NT = NN / 16;
    const int stepb = gridDim.x;
    int t = blockIdx.x;
    if (t >= NT) return;

    const float4* hp = (const float4*)(g_h + (size_t)(t * 16 + row) * 64);
    float4 hv0 = __ldg(hp + cch);
    float4 hv1 = __ldg(hp + cch + 8);
    int p = 0;

    while (true) {
        // stage current tile (tf32) into buffer p
        uint4 u0, u1;
        u0.x = f2tf(hv0.x); u0.y = f2tf(hv0.y); u0.z = f2tf(hv0.z); u0.w = f2tf(hv0.w);
        u1.x = f2tf(hv1.x); u1.y = f2tf(hv1.y); u1.z = f2tf(hv1.z); u1.w = f2tf(hv1.w);
        *(uint4*)(&sH[p][row * 68 + cch * 4]) = u0;
        *(uint4*)(&sH[p][row * 68 + (cch + 8) * 4]) = u1;
        __syncthreads();

        // prefetch next tile's h (overlaps mma)
        const int tn = t + stepb;
        if (tn < NT) {
            const float4* hq = (const float4*)(g_h + (size_t)(tn * 16 + row) * 64);
            hv0 = __ldg(hq + cch);
            hv1 = __ldg(hq + cch + 8);
        }

        float acc[4][4] = {};
#pragma unroll
        for (int ks = 0; ks < 8; ks++) {
            const uint32_t* base = &sH[p][g * 68 + ks * 8 + cp];
            const uint32_t a0 = base[0], a1 = base[8 * 68], a2 = base[4], a3 = base[8 * 68 + 4];
#pragma unroll
            for (int j = 0; j < 4; j++)
                mma_tf32(acc[j][0], acc[j][1], acc[j][2], acc[j][3],
                         a0, a1, a2, a3, Wr[ks][j][0], Wr[ks][j][1]);
        }

        const int row0 = t * 16;
#pragma unroll
        for (int j = 0; j < 4; j++) {
            const int ni = w * 4 + j;
            const int col = (ni & 7) * 8 + 2 * cp;
            float* dst = (ni < 8) ? g_A : g_B;
            *(float2*)(dst + (size_t)(row0 + g) * 64 + col) =
                make_float2(acc[j][0] + bias[j].x, acc[j][1] + bias[j].y);
            *(float2*)(dst + (size_t)(row0 + g + 8) * 64 + col) =
                make_float2(acc[j][2] + bias[j].x, acc[j][3] + bias[j].y);
        }
        if (tn >= NT) break;
        t = tn;
        p ^= 1;
    }
}

// ============ edge conv v3: warp-tile = 1 node, W2 in regs, cross-tile pipeline ============
template <bool REGION>
__global__ void __launch_bounds__(128)
edge_mma_kernel(const int* __restrict__ src, const float* __restrict__ W2,
                const float* __restrict__ b2, const int* __restrict__ labels) {
    __shared__ __align__(16) uint32_t sH[4][16 * 68];   // stride 68 words/row
    __shared__ float sq[REGION ? 4 * RREG * HDIM : 4];

    const int tid = threadIdx.x, lane = tid & 31, w = tid >> 5;
    const int g = lane >> 2, cp = lane & 3;
    const int c = lane & 7, rsub = lane >> 3;

    if (REGION)
        for (int j = tid; j < 4 * RREG * HDIM; j += 128) sq[j] = 0.f;
    __syncthreads();

    // W2 fragments resident in registers (amortized over ~84 tiles/warp)
    uint32_t Wr[8][8][2];
#pragma unroll
    for (int ks = 0; ks < 8; ks++)
#pragma unroll
        for (int ni = 0; ni < 8; ni++) {
            Wr[ks][ni][0] = f2tf(__ldg(W2 + (ks * 8 + cp) * 64 + ni * 8 + g));
            Wr[ks][ni][1] = f2tf(__ldg(W2 + (ks * 8 + cp + 4) * 64 + ni * 8 + g));
        }
    const float bb0 = __ldg(b2 + 2 * lane);
    const float bb1 = __ldg(b2 + 2 * lane + 1);

    uint32_t* sHw = sH[w];
    float* sqw = sq + (REGION ? w * (RREG * HDIM) : 0);

    const int step = gridDim.x * 4;
    int cur = blockIdx.x * 4 + w;          // always < NN (1184 warps << 100K tiles)

    // ---- pipeline prologue: loads for 'cur', srcs for 'cur+step' ----
    int sv0 = __ldg(src + (size_t)cur * DEG + (lane & 15));
    int nx = cur + step; if (nx >= NN) nx = cur;
    int sv_n = __ldg(src + (size_t)nx * DEG + (lane & 15));
    float4 av0 = __ldg((const float4*)(g_A + (size_t)cur * 64) + c);
    float4 av1 = __ldg((const float4*)(g_A + (size_t)cur * 64) + c + 8);
    float4 bq0[4], bq1[4];
#pragma unroll
    for (int q = 0; q < 4; q++) {
        int s = __shfl_sync(0xffffffffu, sv0, q * 4 + rsub);
        const float4* bp = (const float4*)(g_B + (size_t)s * 64);
        bq0[q] = __ldg(bp + c);
        bq1[q] = __ldg(bp + c + 8);
    }

    while (true) {
        // ---- stage h(cur) = relu(A+B) -> tf32 (consumes av/bq) ----
#pragma unroll
        for (int q = 0; q < 4; q++) {
            int r = q * 4 + rsub;
            uint4 h0, h1;
            h0.x = f2tf(fmaxf(av0.x + bq0[q].x, 0.f));
            h0.y = f2tf(fmaxf(av0.y + bq0[q].y, 0.f));
            h0.z = f2tf(fmaxf(av0.z + bq0[q].z, 0.f));
            h0.w = f2tf(fmaxf(av0.w + bq0[q].w, 0.f));
            h1.x = f2tf(fmaxf(av1.x + bq1[q].x, 0.f));
            h1.y = f2tf(fmaxf(av1.y + bq1[q].y, 0.f));
            h1.z = f2tf(fmaxf(av1.z + bq1[q].z, 0.f));
            h1.w = f2tf(fmaxf(av1.w + bq1[q].w, 0.f));
            *(uint4*)(sHw + r * 68 + c * 4) = h0;
            *(uint4*)(sHw + r * 68 + (c + 8) * 4) = h1;
        }
        __syncwarp();

        // ---- prefetch tile nx (A, B) and srcs for nx+step; overlaps mma below ----
        int n2 = nx + step; if (n2 >= NN) n2 = nx;
        int sv_p = __ldg(src + (size_t)n2 * DEG + (lane & 15));
        av0 = __ldg((const float4*)(g_A + (size_t)nx * 64) + c);
        av1 = __ldg((const float4*)(g_A + (size_t)nx * 64) + c + 8);
#pragma unroll
        for (int q = 0; q < 4; q++) {
            int s = __shfl_sync(0xffffffffu, sv_n, q * 4 + rsub);
            const float4* bp = (const float4*)(g_B + (size_t)s * 64);
            bq0[q] = __ldg(bp + c);
            bq1[q] = __ldg(bp + c + 8);
        }

        // ---- mma on staged h(cur); independent of in-flight prefetch ----
        float acc[8][4] = {};
#pragma unroll
        for (int ks = 0; ks < 8; ks++) {
            const uint32_t* base = sHw + g * 68 + ks * 8 + cp;   // conflict-free
            uint32_t a0 = base[0], a1 = base[8 * 68], a2 = base[4], a3 = base[8 * 68 + 4];
#pragma unroll
            for (int ni = 0; ni < 8; ni++)
                mma_tf32(acc[ni][0], acc[ni][1], acc[ni][2], acc[ni][3],
                         a0, a1, a2, a3, Wr[ks][ni][0], Wr[ks][ni][1]);
        }
        __syncwarp();

        // ---- segment-max over 16 rows; lane owns cols (2*lane, 2*lane+1) ----
        float vx = 0.f, vy = 0.f;
#pragma unroll
        for (int ni = 0; ni < 8; ni++) {
            float v0 = fmaxf(acc[ni][0], acc[ni][2]);
            float v1 = fmaxf(acc[ni][1], acc[ni][3]);
            v0 = fmaxf(v0, __shfl_xor_sync(0xffffffffu, v0, 4));
            v1 = fmaxf(v1, __shfl_xor_sync(0xffffffffu, v1, 4));
            v0 = fmaxf(v0, __shfl_xor_sync(0xffffffffu, v0, 8));
            v1 = fmaxf(v1, __shfl_xor_sync(0xffffffffu, v1, 8));
            v0 = fmaxf(v0, __shfl_xor_sync(0xffffffffu, v0, 16));
            v1 = fmaxf(v1, __shfl_xor_sync(0xffffffffu, v1, 16));
            if ((lane >> 2) == ni) { vx = v0; vy = v1; }
        }
        const float o0 = fmaxf(vx + bb0, 0.f);
        const float o1 = fmaxf(vy + bb1, 0.f);
        if (!REGION) {
            *(float2*)(g_h + (size_t)cur * 64 + 2 * lane) = make_float2(o0, o1);
        } else {
            const int lab = __ldg(labels + cur);
            float* p = sqw + lab * 64 + 2 * lane;
            float2 t = *(float2*)p;
            *(float2*)p = make_float2(t.x + o0, t.y + o1);
        }

        // ---- rotate pipeline state ----
        int nc = cur + step;
        if (nc >= NN) break;
        cur = nc;
        nx = cur + step; if (nx >= NN) nx = cur;
        sv_n = sv_p;
    }

    if (REGION) {
        __syncthreads();
        for (int j = tid; j < RREG * HDIM; j += 128)
            atomicAdd(&g_qsum[j],
                      sq[j] + sq[RREG * HDIM + j] + sq[2 * RREG * HDIM + j] + sq[3 * RREG * HDIM + j]);
    }
}

// ============ tail v2: 512 threads, (region, col) parallel ============
__global__ void __launch_bounds__(512)
tail_kernel(const int* __restrict__ qe, int Eq,
            const float* __restrict__ W31, const float* __restrict__ b31,
            const float* __restrict__ W32, const float* __restrict__ b32,
            const float* __restrict__ W41, const float* __restrict__ b41,
            const float* __restrict__ W42, const float* __restrict__ b42,
            const float* __restrict__ linW, const float* __restrict__ linb,
            float* __restrict__ out) {
    __shared__ float q[RREG][HDIM], Aa[RREG][HDIM], Bb[RREG][HDIM];
    __shared__ float semb[HDIM];
    const int tid = threadIdx.x;
    const int r = tid >> 6, c = tid & 63;
    const float NEGINF = __int_as_float(0xff800000);

    q[r][c] = g_qsum[r * HDIM + c] / fmaxf((float)g_qcnt[r], 1.f);
    __syncthreads();

#pragma unroll
    for (int layer = 0; layer < 2; layer++) {
        const float* W1  = layer ? W41 : W31;
        const float* b1v = layer ? b41 : b31;
        const float* W2  = layer ? W42 : W32;
        const float* b2v = layer ? b42 : b32;

        float a = 0.f, b = 0.f;
#pragma unroll 8
        for (int k = 0; k < HDIM; k++) {
            float f = q[r][k];
            float wa = __ldg(W1 + k * HDIM + c);
            float wb = __ldg(W1 + (k + HDIM) * HDIM + c);
            a = fmaf(f, wa - wb, a);
            b = fmaf(f, wb, b);
        }
        Aa[r][c] = a + __ldg(b1v + c);
        Bb[r][c] = b;
        __syncthreads();

        float mm = NEGINF;
        for (int e = 0; e < Eq; e++) {
            int s = __ldg(qe + e);
            int t = __ldg(qe + Eq + e);
            if (t == r) {
                float acc = 0.f;
#pragma unroll 8
                for (int k = 0; k < HDIM; k++) {
                    float hk = fmaxf(Aa[r][k] + Bb[s][k], 0.f);
                    acc = fmaf(hk, __ldg(W2 + k * HDIM + c), acc);
                }
                mm = fmaxf(mm, acc);
            }
        }
        __syncthreads();
        q[r][c] = fmaxf((mm == NEGINF) ? 0.f : (mm + __ldg(b2v + c)), 0.f);
        __syncthreads();
    }

    if (r == 0) {
        float e = 0.f;
#pragma unroll
        for (int rr = 0; rr < RREG; rr++) e += q[rr][c];
        semb[c] = e;
    }
    __syncthreads();
    if (tid < 8) {
        float o = __ldg(linb + tid);
#pragma unroll 8
        for (int k = 0; k < HDIM; k++) o = fmaf(semb[k], __ldg(linW + k * 8 + tid), o);
        out[tid] = o;
    }
}

// ---------------------------------------------------------------------
extern "C" void kernel_launch(void* const* d_in, const int* in_sizes, int n_in,
                              void* d_out, int out_size) {
    const float* x      = (const float*)d_in[0];
    const float* pos    = (const float*)d_in[1];
    const int*   ei     = (const int*)d_in[2];
    const int*   labels = (const int*)d_in[3];
    const int*   qe     = (const int*)d_in[4];
    const float* W11 = (const float*)d_in[5],  *b11 = (const float*)d_in[6];
    const float* W12 = (const float*)d_in[7],  *b12 = (const float*)d_in[8];
    const float* W21 = (const float*)d_in[9],  *b21 = (const float*)d_in[10];
    const float* W22 = (const float*)d_in[11], *b22 = (const float*)d_in[12];
    const float* W31 = (const float*)d_in[13], *b31 = (const float*)d_in[14];
    const float* W32 = (const float*)d_in[15], *b32 = (const float*)d_in[16];
    const float* W41 = (const float*)d_in[17], *b41 = (const float*)d_in[18];
    const float* W42 = (const float*)d_in[19], *b42 = (const float*)d_in[20];
    const float* linW = (const float*)d_in[21], *linb = (const float*)d_in[22];

    int Eq = in_sizes[4] / 2;
    const int* src = ei;   // row 0 = src; row 1 (tgt) = repeat(arange(N),16)

    init_kernel<<<1, 512>>>();
    count_kernel<<<256, 256>>>(labels);
    node1_kernel<<<740, 128>>>(x, pos, W11, b11);
    edge_mma_kernel<false><<<296, 128>>>(src, W12, b12, nullptr);
    node2_mma_kernel<<<592, 128>>>(W21, b21);
    edge_mma_kernel<true><<<296, 128>>>(src, W22, b22, labels);
    tail_kernel<<<1, 512>>>(qe, Eq, W31, b31, W32, b32, W41, b41, W42, b42,
                            linW, linb, (float*)d_out);
}

// round 8
// speedup vs baseline: 3.4327x; 1.0475x over previous
#include <cuda_runtime.h>
#include <cstdint>
#include <math.h>

#define NN    100000
#define DEG   16
#define FDIM  16
#define PDIM  3
#define HDIM  64
#define RREG  8
#define DIN1  19

// -------- scratch (no allocations allowed; static device globals) --------
__device__ float g_A[NN * HDIM];      // per-node "center" term
__device__ float g_B[NN * HDIM];      // per-node "neighbor" term
__device__ float g_h[NN * HDIM];      // conv1 output
__device__ float g_qsum[RREG * HDIM]; // region feature sums
__device__ int   g_qcnt[RREG];        // region counts

__device__ __forceinline__ uint32_t f2tf(float f) {
    uint32_t r;
    asm("cvt.rna.tf32.f32 %0, %1;" : "=r"(r) : "f"(f));
    return r;
}

// m16n8k8 tf32 mma (baseline PTX, valid on compute_103)
__device__ __forceinline__ void mma_tf32(float& c0, float& c1, float& c2, float& c3,
                                         uint32_t a0, uint32_t a1, uint32_t a2, uint32_t a3,
                                         uint32_t b0, uint32_t b1) {
    asm volatile("mma.sync.aligned.m16n8k8.row.col.f32.tf32.tf32.f32 "
                 "{%0,%1,%2,%3}, {%4,%5,%6,%7}, {%8,%9}, {%0,%1,%2,%3};"
                 : "+f"(c0), "+f"(c1), "+f"(c2), "+f"(c3)
                 : "r"(a0), "r"(a1), "r"(a2), "r"(a3), "r"(b0), "r"(b1));
}

// ============ node1: weights in registers, shfl broadcast, pipelined; block 0 inits qsum/qcnt ============
__global__ void __launch_bounds__(128)
node1_kernel(const float* __restrict__ x, const float* __restrict__ pos,
             const float* __restrict__ W1, const float* __restrict__ b1) {
    const int tid = threadIdx.x, lane = tid & 31;

    if (blockIdx.x == 0) {                 // fused init — FULL coverage (replay-safe)
        for (int j = tid; j < RREG * HDIM; j += 128) g_qsum[j] = 0.f;
        if (tid < RREG) g_qcnt[tid] = 0;
    }

    float wA[DIN1][2], wB[DIN1][2];
#pragma unroll
    for (int k = 0; k < DIN1; k++) {
        float wb0 = __ldg(W1 + (k + DIN1) * HDIM + lane);
        float wb1 = __ldg(W1 + (k + DIN1) * HDIM + 32 + lane);
        wA[k][0] = __ldg(W1 + k * HDIM + lane) - wb0;
        wA[k][1] = __ldg(W1 + k * HDIM + 32 + lane) - wb1;
        wB[k][0] = wb0;
        wB[k][1] = wb1;
    }
    const float ba0 = __ldg(b1 + lane), ba1 = __ldg(b1 + 32 + lane);

    const int step = gridDim.x * 4;
    int i = blockIdx.x * 4 + (tid >> 5);
    if (i >= NN) return;

    float f = 0.f;
    if (lane < FDIM)            f = __ldg(x + (size_t)i * FDIM + lane);
    else if (lane < DIN1)       f = __ldg(pos + (size_t)i * PDIM + (lane - FDIM));

    while (true) {
        const int nx = i + step;
        float fn = 0.f;
        if (nx < NN) {
            if (lane < FDIM)      fn = __ldg(x + (size_t)nx * FDIM + lane);
            else if (lane < DIN1) fn = __ldg(pos + (size_t)nx * PDIM + (lane - FDIM));
        }
        float a0 = 0.f, a1 = 0.f, b0 = 0.f, b1v = 0.f;
#pragma unroll
        for (int k = 0; k < DIN1; k++) {
            const float fk = __shfl_sync(0xffffffffu, f, k);
            a0 = fmaf(fk, wA[k][0], a0);
            a1 = fmaf(fk, wA[k][1], a1);
            b0 = fmaf(fk, wB[k][0], b0);
            b1v = fmaf(fk, wB[k][1], b1v);
        }
        g_A[(size_t)i * 64 + lane]      = a0 + ba0;
        g_A[(size_t)i * 64 + 32 + lane] = a1 + ba1;
        g_B[(size_t)i * 64 + lane]      = b0;
        g_B[(size_t)i * 64 + 32 + lane] = b1v;
        if (nx >= NN) break;
        i = nx;
        f = fn;
    }
}

// ============ node2: block tile of 16 rows, W-frags in regs (split over N by warp) ============
__global__ void __launch_bounds__(128)
node2_mma_kernel(const float* __restrict__ W1, const float* __restrict__ b1) {
    __shared__ __align__(16) uint32_t sH[2][16 * 68];
    const int tid = threadIdx.x, lane = tid & 31, w = tid >> 5;
    const int g = lane >> 2, cp = lane & 3;
    const int row = tid >> 3, cch = tid & 7;

    uint32_t Wr[8][4][2];
    float2 bias[4];
#pragma unroll
    for (int ks = 0; ks < 8; ks++)
#pragma unroll
        for (int j = 0; j < 4; j++) {
            const int ni = w * 4 + j;
            const int n = ni * 8 + g;
#pragma unroll
            for (int hh = 0; hh < 2; hh++) {
                const int k = ks * 8 + cp + hh * 4;
                float v;
                if (n < 64) v = __ldg(W1 + k * 64 + n) - __ldg(W1 + (k + 64) * 64 + n);
                else        v = __ldg(W1 + (k + 64) * 64 + (n - 64));
                Wr[ks][j][hh] = f2tf(v);
            }
        }
#pragma unroll
    for (int j = 0; j < 4; j++) {
        const int ni = w * 4 + j;
        const int col = (ni & 7) * 8 + 2 * cp;
        bias[j] = (ni < 8) ? *(const float2*)(b1 + col) : make_float2(0.f, 0.f);
    }

    const int NT = NN / 16;
    const int stepb = gridDim.x;
    int t = blockIdx.x;
    if (t >= NT) return;

    const float4* hp = (const float4*)(g_h + (size_t)(t * 16 + row) * 64);
    float4 hv0 = __ldg(hp + cch);
    float4 hv1 = __ldg(hp + cch + 8);
    int p = 0;

    while (true) {
        uint4 u0, u1;
        u0.x = f2tf(hv0.x); u0.y = f2tf(hv0.y); u0.z = f2tf(hv0.z); u0.w = f2tf(hv0.w);
        u1.x = f2tf(hv1.x); u1.y = f2tf(hv1.y); u1.z = f2tf(hv1.z); u1.w = f2tf(hv1.w);
        *(uint4*)(&sH[p][row * 68 + cch * 4]) = u0;
        *(uint4*)(&sH[p][row * 68 + (cch + 8) * 4]) = u1;
        __syncthreads();

        const int tn = t + stepb;
        if (tn < NT) {
            const float4* hq = (const float4*)(g_h + (size_t)(tn * 16 + row) * 64);
            hv0 = __ldg(hq + cch);
            hv1 = __ldg(hq + cch + 8);
        }

        float acc[4][4] = {};
#pragma unroll
        for (int ks = 0; ks < 8; ks++) {
            const uint32_t* base = &sH[p][g * 68 + ks * 8 + cp];
            const uint32_t a0 = base[0], a1 = base[8 * 68], a2 = base[4], a3 = base[8 * 68 + 4];
#pragma unroll
            for (int j = 0; j < 4; j++)
                mma_tf32(acc[j][0], acc[j][1], acc[j][2], acc[j][3],
                         a0, a1, a2, a3, Wr[ks][j][0], Wr[ks][j][1]);
        }

        const int row0 = t * 16;
#pragma unroll
        for (int j = 0; j < 4; j++) {
            const int ni = w * 4 + j;
            const int col = (ni & 7) * 8 + 2 * cp;
            float* dst = (ni < 8) ? g_A : g_B;
            *(float2*)(dst + (size_t)(row0 + g) * 64 + col) =
                make_float2(acc[j][0] + bias[j].x, acc[j][1] + bias[j].y);
            *(float2*)(dst + (size_t)(row0 + g + 8) * 64 + col) =
                make_float2(acc[j][2] + bias[j].x, acc[j][3] + bias[j].y);
        }
        if (tn >= NT) break;
        t = tn;
        p ^= 1;
    }
}

// ============ edge conv v4: warp-pair, 2 nodes x 32 cols per warp, W2 half in regs ============
// Pair of warps shares a 32-row staged tile (both nodes); warp wl computes cols [wl*32, wl*32+32).
template <bool REGION>
__global__ void __launch_bounds__(128, 3)
edge_mma_kernel(const int* __restrict__ src, const float* __restrict__ W2,
                const float* __restrict__ b2, const int* __restrict__ labels) {
    __shared__ __align__(16) uint32_t sH[2][2][32 * 68];   // [pair][buf][row*68]
    __shared__ float sq[REGION ? 4 * RREG * HDIM : 4];
    __shared__ int   scnt[REGION ? 4 * RREG : 4];

    const int tid = threadIdx.x, lane = tid & 31, w = tid >> 5;
    const int pair = w >> 1, wl = w & 1;
    const int g = lane >> 2, cp = lane & 3;
    const int c = lane & 7, rsub = lane >> 3;
    const int colbase = wl * 32;
    const int l15 = lane & 15;

    if (REGION) {
        for (int j = tid; j < 4 * RREG * HDIM; j += 128) sq[j] = 0.f;
        if (tid < 4 * RREG) scnt[tid] = 0;
    }
    __syncthreads();

    // W2 columns [colbase, colbase+32) in registers (64 regs)
    uint32_t Wr[8][4][2];
#pragma unroll
    for (int ks = 0; ks < 8; ks++)
#pragma unroll
        for (int ni = 0; ni < 4; ni++) {
            const int n = colbase + ni * 8 + g;
            Wr[ks][ni][0] = f2tf(__ldg(W2 + (ks * 8 + cp) * 64 + n));
            Wr[ks][ni][1] = f2tf(__ldg(W2 + (ks * 8 + cp + 4) * 64 + n));
        }
    const float bb0 = __ldg(b2 + colbase + 2 * l15);
    const float bb1 = __ldg(b2 + colbase + 2 * l15 + 1);

    float* sqw = sq + (REGION ? w * (RREG * HDIM) : 0);
    const int barid = pair + 1;

    const int step = gridDim.x * 4;                 // nodes per iteration across chip
    int n0 = (blockIdx.x * 2 + pair) * 2;           // this pair's first node
    int node = n0 + wl;                             // the node THIS warp gathers

    // ---- prologue: loads for 'node', srcs for 'node+step' ----
    int sv = __ldg(src + (size_t)node * DEG + l15);
    int nxn = node + step; if (nxn >= NN) nxn = node;
    int sv_n = __ldg(src + (size_t)nxn * DEG + l15);
    float4 av0 = __ldg((const float4*)(g_A + (size_t)node * 64) + c);
    float4 av1 = __ldg((const float4*)(g_A + (size_t)node * 64) + c + 8);
    float4 bq0[4], bq1[4];
#pragma unroll
    for (int q = 0; q < 4; q++) {
        int s = __shfl_sync(0xffffffffu, sv, q * 4 + rsub);
        const float4* bp = (const float4*)(g_B + (size_t)s * 64);
        bq0[q] = __ldg(bp + c);
        bq1[q] = __ldg(bp + c + 8);
    }

    int p = 0;
    while (true) {
        uint32_t* sHp = sH[pair][p];
        // ---- stage h(node) rows [wl*16, wl*16+16) ----
#pragma unroll
        for (int q = 0; q < 4; q++) {
            const int r = wl * 16 + q * 4 + rsub;
            uint4 h0, h1;
            h0.x = f2tf(fmaxf(av0.x + bq0[q].x, 0.f));
            h0.y = f2tf(fmaxf(av0.y + bq0[q].y, 0.f));
            h0.z = f2tf(fmaxf(av0.z + bq0[q].z, 0.f));
            h0.w = f2tf(fmaxf(av0.w + bq0[q].w, 0.f));
            h1.x = f2tf(fmaxf(av1.x + bq1[q].x, 0.f));
            h1.y = f2tf(fmaxf(av1.y + bq1[q].y, 0.f));
            h1.z = f2tf(fmaxf(av1.z + bq1[q].z, 0.f));
            h1.w = f2tf(fmaxf(av1.w + bq1[q].w, 0.f));
            *(uint4*)(sHp + r * 68 + c * 4) = h0;
            *(uint4*)(sHp + r * 68 + (c + 8) * 4) = h1;
        }

        if (REGION && lane == 0)
            scnt[w * RREG + __ldg(labels + node)]++;   // each node counted once (by its gather warp)

        // ---- prefetch next tile (overlaps barrier + mma) ----
        {
            int n2 = nxn + step; if (n2 >= NN) n2 = nxn;
            int sv_p = __ldg(src + (size_t)n2 * DEG + l15);
            av0 = __ldg((const float4*)(g_A + (size_t)nxn * 64) + c);
            av1 = __ldg((const float4*)(g_A + (size_t)nxn * 64) + c + 8);
#pragma unroll
            for (int q = 0; q < 4; q++) {
                int s = __shfl_sync(0xffffffffu, sv_n, q * 4 + rsub);
                const float4* bp = (const float4*)(g_B + (size_t)s * 64);
                bq0[q] = __ldg(bp + c);
                bq1[q] = __ldg(bp + c + 8);
            }
            sv_n = sv_p;
        }

        // ---- pair barrier: both warps' 16 rows staged (bar drains STS) ----
        asm volatile("bar.sync %0, 64;" :: "r"(barid) : "memory");

        // ---- mma: 2 m-tiles (nodes) x 4 n-tiles (this warp's cols) x 8 k ----
        float acc[2][4][4] = {};
#pragma unroll
        for (int ks = 0; ks < 8; ks++) {
            const uint32_t* base = sHp + g * 68 + ks * 8 + cp;   // conflict-free
            const uint32_t a00 = base[0],        a01 = base[8 * 68];
            const uint32_t a02 = base[4],        a03 = base[8 * 68 + 4];
            const uint32_t a10 = base[16 * 68],  a11 = base[24 * 68];
            const uint32_t a12 = base[16 * 68 + 4], a13 = base[24 * 68 + 4];
#pragma unroll
            for (int ni = 0; ni < 4; ni++) {
                mma_tf32(acc[0][ni][0], acc[0][ni][1], acc[0][ni][2], acc[0][ni][3],
                         a00, a01, a02, a03, Wr[ks][ni][0], Wr[ks][ni][1]);
                mma_tf32(acc[1][ni][0], acc[1][ni][1], acc[1][ni][2], acc[1][ni][3],
                         a10, a11, a12, a13, Wr[ks][ni][0], Wr[ks][ni][1]);
            }
        }

        // ---- segment-max: butterfly with value-set halving ----
        // value (mi, ni, p2) -> final owner lane (g2=mi, g1g0=ni, cp), col=colbase+2*(lane&15)
        const int g0 = g & 1, g1 = (g >> 1) & 1, g2 = g >> 2;
        float v[2][4][2];
#pragma unroll
        for (int mi = 0; mi < 2; mi++)
#pragma unroll
            for (int ni = 0; ni < 4; ni++) {
                v[mi][ni][0] = fmaxf(acc[mi][ni][0], acc[mi][ni][2]);
                v[mi][ni][1] = fmaxf(acc[mi][ni][1], acc[mi][ni][3]);
            }
        // L1: xor 4 resolves ni bit0 (keep ni0 == g0)
        float w1v[2][2][2];
#pragma unroll
        for (int mi = 0; mi < 2; mi++)
#pragma unroll
            for (int nh = 0; nh < 2; nh++)
#pragma unroll
                for (int p2 = 0; p2 < 2; p2++) {
                    const float snd = g0 ? v[mi][2 * nh][p2] : v[mi][2 * nh + 1][p2];
                    const float kp  = g0 ? v[mi][2 * nh + 1][p2] : v[mi][2 * nh][p2];
                    w1v[mi][nh][p2] = fmaxf(kp, __shfl_xor_sync(0xffffffffu, snd, 4));
                }
        // L2: xor 8 resolves ni bit1 (keep nh == g1)
        float w2v[2][2];
#pragma unroll
        for (int mi = 0; mi < 2; mi++)
#pragma unroll
            for (int p2 = 0; p2 < 2; p2++) {
                const float snd = g1 ? w1v[mi][0][p2] : w1v[mi][1][p2];
                const float kp  = g1 ? w1v[mi][1][p2] : w1v[mi][0][p2];
                w2v[mi][p2] = fmaxf(kp, __shfl_xor_sync(0xffffffffu, snd, 8));
            }
        // L3: xor 16 resolves mi (keep mi == g2)
        float fx, fy;
        {
            const float snd0 = g2 ? w2v[0][0] : w2v[1][0];
            const float kp0  = g2 ? w2v[1][0] : w2v[0][0];
            fx = fmaxf(kp0, __shfl_xor_sync(0xffffffffu, snd0, 16));
            const float snd1 = g2 ? w2v[0][1] : w2v[1][1];
            const float kp1  = g2 ? w2v[1][1] : w2v[0][1];
            fy = fmaxf(kp1, __shfl_xor_sync(0xffffffffu, snd1, 16));
        }
        const float o0 = fmaxf(fx + bb0, 0.f);
        const float o1 = fmaxf(fy + bb1, 0.f);

        const int node_out = n0 + (lane >> 4);
        const int col = colbase + 2 * l15;
        if (!REGION) {
            *(float2*)(g_h + (size_t)node_out * 64 + col) = make_float2(o0, o1);
        } else {
            const int lab = __ldg(labels + node_out);
            float* pp = sqw + lab * 64 + col;
            if (lane < 16) { pp[0] += o0; pp[1] += o1; }
            __syncwarp();
            if (lane >= 16) { pp[0] += o0; pp[1] += o1; }
        }

        // ---- rotate ----
        const int nn0 = n0 + step;
        if (nn0 >= NN) break;
        n0 = nn0;
        node = n0 + wl;
        nxn = node + step; if (nxn >= NN) nxn = node;
        p ^= 1;
    }

    if (REGION) {
        __syncthreads();
        for (int j = tid; j < RREG * HDIM; j += 128)
            atomicAdd(&g_qsum[j],
                      sq[j] + sq[RREG * HDIM + j] + sq[2 * RREG * HDIM + j] + sq[3 * RREG * HDIM + j]);
        if (tid < RREG)
            atomicAdd(&g_qcnt[tid],
                      scnt[tid] + scnt[RREG + tid] + scnt[2 * RREG + tid] + scnt[3 * RREG + tid]);
    }
}

// ============ tail: 512 threads, (region, col) parallel ============
__global__ void __launch_bounds__(512)
tail_kernel(const int* __restrict__ qe, int Eq,
            const float* __restrict__ W31, const float* __restrict__ b31,
            const float* __restrict__ W32, const float* __restrict__ b32,
            const float* __restrict__ W41, const float* __restrict__ b41,
            const float* __restrict__ W42, const float* __restrict__ b42,
            const float* __restrict__ linW, const float* __restrict__ linb,
            float* __restrict__ out) {
    __shared__ float q[RREG][HDIM], Aa[RREG][HDIM], Bb[RREG][HDIM];
    __shared__ float semb[HDIM];
    const int tid = threadIdx.x;
    const int r = tid >> 6, c = tid & 63;
    const float NEGINF = __int_as_float(0xff800000);

    q[r][c] = g_qsum[r * HDIM + c] / fmaxf((float)g_qcnt[r], 1.f);
    __syncthreads();

#pragma unroll
    for (int layer = 0; layer < 2; layer++) {
        const float* W1  = layer ? W41 : W31;
        const float* b1v = layer ? b41 : b31;
        const float* W2  = layer ? W42 : W32;
        const float* b2v = layer ? b42 : b32;

        float a = 0.f, b = 0.f;
#pragma unroll 8
        for (int k = 0; k < HDIM; k++) {
            float f = q[r][k];
            float wa = __ldg(W1 + k * HDIM + c);
            float wb = __ldg(W1 + (k + HDIM) * HDIM + c);
            a = fmaf(f, wa - wb, a);
            b = fmaf(f, wb, b);
        }
        Aa[r][c] = a + __ldg(b1v + c);
        Bb[r][c] = b;
        __syncthreads();

        float mm = NEGINF;
        for (int e = 0; e < Eq; e++) {
            int s = __ldg(qe + e);
            int t = __ldg(qe + Eq + e);
            if (t == r) {
                float acc = 0.f;
#pragma unroll 8
                for (int k = 0; k < HDIM; k++) {
                    float hk = fmaxf(Aa[r][k] + Bb[s][k], 0.f);
                    acc = fmaf(hk, __ldg(W2 + k * HDIM + c), acc);
                }
                mm = fmaxf(mm, acc);
            }
        }
        __syncthreads();
        q[r][c] = fmaxf((mm == NEGINF) ? 0.f : (mm + __ldg(b2v + c)), 0.f);
        __syncthreads();
    }

    if (r == 0) {
        float e = 0.f;
#pragma unroll
        for (int rr = 0; rr < RREG; rr++) e += q[rr][c];
        semb[c] = e;
    }
    __syncthreads();
    if (tid < 8) {
        float o = __ldg(linb + tid);
#pragma unroll 8
        for (int k = 0; k < HDIM; k++) o = fmaf(semb[k], __ldg(linW + k * 8 + tid), o);
        out[tid] = o;
    }
}

// ---------------------------------------------------------------------
extern "C" void kernel_launch(void* const* d_in, const int* in_sizes, int n_in,
                              void* d_out, int out_size) {
    const float* x      = (const float*)d_in[0];
    const float* pos    = (const float*)d_in[1];
    const int*   ei     = (const int*)d_in[2];
    const int*   labels = (const int*)d_in[3];
    const int*   qe     = (const int*)d_in[4];
    const float* W11 = (const float*)d_in[5],  *b11 = (const float*)d_in[6];
    const float* W12 = (const float*)d_in[7],  *b12 = (const float*)d_in[8];
    const float* W21 = (const float*)d_in[9],  *b21 = (const float*)d_in[10];
    const float* W22 = (const float*)d_in[11], *b22 = (const float*)d_in[12];
    const float* W31 = (const float*)d_in[13], *b31 = (const float*)d_in[14];
    const float* W32 = (const float*)d_in[15], *b32 = (const float*)d_in[16];
    const float* W41 = (const float*)d_in[17], *b41 = (const float*)d_in[18];
    const float* W42 = (const float*)d_in[19], *b42 = (const float*)d_in[20];
    const float* linW = (const float*)d_in[21], *linb = (const float*)d_in[22];

    int Eq = in_sizes[4] / 2;
    const int* src = ei;   // row 0 = src; row 1 (tgt) = repeat(arange(N),16)

    node1_kernel<<<740, 128>>>(x, pos, W11, b11);                 // + init fused (block 0)
    edge_mma_kernel<false><<<444, 128>>>(src, W12, b12, nullptr);
    node2_mma_kernel<<<592, 128>>>(W21, b21);
    edge_mma_kernel<true><<<444, 128>>>(src, W22, b22, labels);   // + count fused
    tail_kernel<<<1, 512>>>(qe, Eq, W31, b31, W32, b32, W41, b41, W42, b42,
                            linW, linb, (float*)d_out);
}